// round 8
// baseline (speedup 1.0000x reference)
#include <cuda_runtime.h>
#include <cuda_bf16.h>
#include <cstdint>
#include <math.h>

#define NBATCH 64
#define NT     512
#define NROWS  (NBATCH * NT)
#define NB     128

// ---------------- device scratch ----------------
__device__ float g_pre1[NROWS * 1024];
__device__ float g_pre2[NROWS * 512];
__device__ float g_v1T[1024 * 64];             // [h][b]
__device__ float g_memT[2][256 * 64];          // [m][b] double-buffered
__device__ float g_Apart[8 * 1024 * 64];       // [mc][h][b]
__device__ float g_Bpart[24 * 128 * 64];       // [kc][o][b]
__device__ float g_bias1[1024];
__device__ float g_bias2[512];
// tree barrier state
__device__ unsigned g_cntG[8 * 32];            // 8 group counters, 128B apart
__device__ unsigned g_cntR;
__device__ volatile unsigned g_epoch;
// bf16 split operands (K-concat trick)
__device__ __nv_bfloat16 g_X3[NROWS * 1536];   // [Ah|Ah|Al]
__device__ __nv_bfloat16 g_W013[1024 * 1536];  // [Wh|Wl|Wh]
__device__ __nv_bfloat16 g_W023[512 * 1536];
__device__ __nv_bfloat16 g_Wt3[384 * 3840];    // tail weights [Wh|Wl|Wh], K=1280
__device__ __nv_bfloat16 g_At3[NROWS * 3840];  // tail A [Ah|Ah|Al], filled by loop

// ---------------- prep ----------------
__global__ void prep_kernel(const float* __restrict__ b01, const float* __restrict__ bm1,
                            const float* __restrict__ b02, const float* __restrict__ b12,
                            const float* __restrict__ bm2, const float* __restrict__ memory) {
    int i = blockIdx.x * blockDim.x + threadIdx.x;
    int n = gridDim.x * blockDim.x;
    if (i == 0) { g_cntR = 0u; g_epoch = 0u; }
    if (i < 8) g_cntG[i * 32] = 0u;
    for (int j = i; j < 1024; j += n) g_bias1[j] = b01[j] + bm1[j];
    for (int j = i; j < 512; j += n) g_bias2[j] = b02[j] + b12[j] + bm2[j];
    for (int j = i; j < 256 * 64; j += n) {
        int m = j & 255, b = j >> 8;
        float x = memory[j];                    // memory[b][m]
        g_memT[0][m * 64 + b] = x;
        __nv_bfloat16 h = __float2bfloat16(x);
        __nv_bfloat16 l = __float2bfloat16(x - __bfloat162float(h));
        size_t base = (size_t)(b * NT) * 3840;  // row t=0
        g_At3[base + 1024 + m] = h;
        g_At3[base + 2304 + m] = h;
        g_At3[base + 3584 + m] = l;
    }
}

// split fp32 -> bf16 hi/lo, K-concat. aMode: [h|h|l]  else (W): [h|l|h]
__global__ void split3_kernel(const float* __restrict__ src, __nv_bfloat16* __restrict__ dst,
                              int K, int total, int aMode) {
    for (int i = blockIdx.x * blockDim.x + threadIdx.x; i < total; i += gridDim.x * blockDim.x) {
        int r = i / K, k = i % K;
        float x = src[i];
        __nv_bfloat16 h = __float2bfloat16(x);
        __nv_bfloat16 l = __float2bfloat16(x - __bfloat162float(h));
        __nv_bfloat16* d = dst + (size_t)r * 3 * K + k;
        d[0] = h;
        d[K] = aMode ? h : l;
        d[2 * K] = aMode ? l : h;
    }
}

// tail W: rows o=0..383 map to W12[o+128], Wm2[o+128]; [Wh|Wl|Wh] over K=1280
__global__ void splitWtail_kernel(const float* __restrict__ W12, const float* __restrict__ Wm2) {
    for (int i = blockIdx.x * blockDim.x + threadIdx.x; i < 384 * 1280; i += gridDim.x * blockDim.x) {
        int o = i / 1280, k = i % 1280;
        float x = (k < 1024) ? W12[(o + 128) * 1024 + k] : Wm2[(o + 128) * 256 + (k - 1024)];
        __nv_bfloat16 h = __float2bfloat16(x);
        __nv_bfloat16 l = __float2bfloat16(x - __bfloat162float(h));
        __nv_bfloat16* d = g_Wt3 + (size_t)o * 3840 + k;
        d[0] = h; d[1280] = l; d[2560] = h;
    }
}

// ---------------- bf16 tensor-core GEMM (passing) ----------------
__global__ void __launch_bounds__(256) hgemm_kernel(const __nv_bfloat16* __restrict__ A,
                                                    const __nv_bfloat16* __restrict__ W, int K,
                                                    float* __restrict__ C, int ldc,
                                                    const float* __restrict__ bias,
                                                    const float* __restrict__ addm, int addld,
                                                    int swapxy) {
    __shared__ __nv_bfloat16 sA[2][128][40];
    __shared__ __nv_bfloat16 sW[2][128][40];
    const int tid = threadIdx.x;
    const int bx = swapxy ? blockIdx.y : blockIdx.x;
    const int by = swapxy ? blockIdx.x : blockIdx.y;
    const int m0 = bx * 128, n0 = by * 128;
    const int warp = tid >> 5, lane = tid & 31;
    const int wm = (warp >> 1) * 32, wn = (warp & 1) * 64;
    const int lr = tid >> 1, lc = (tid & 1) * 16;
    float acc[2][8][4] = {};
    const __nv_bfloat16* Ag = A + (size_t)(m0 + lr) * K + lc;
    const __nv_bfloat16* Wg = W + (size_t)(n0 + lr) * K + lc;
    uint4 ra0 = *(const uint4*)Ag, ra1 = *(const uint4*)(Ag + 8);
    uint4 rw0 = *(const uint4*)Wg, rw1 = *(const uint4*)(Wg + 8);
    *(uint4*)&sA[0][lr][lc] = ra0; *(uint4*)&sA[0][lr][lc + 8] = ra1;
    *(uint4*)&sW[0][lr][lc] = rw0; *(uint4*)&sW[0][lr][lc + 8] = rw1;
    __syncthreads();
    const int nsteps = K / 32;
    for (int s = 0; s < nsteps; s++) {
        const int cur = s & 1;
        if (s + 1 < nsteps) {
            const __nv_bfloat16* An = Ag + (size_t)(s + 1) * 32;
            const __nv_bfloat16* Wn = Wg + (size_t)(s + 1) * 32;
            ra0 = *(const uint4*)An; ra1 = *(const uint4*)(An + 8);
            rw0 = *(const uint4*)Wn; rw1 = *(const uint4*)(Wn + 8);
        }
#pragma unroll
        for (int kf = 0; kf < 2; kf++) {
            const int acol = kf * 16 + (lane & 3) * 2;
            const int arow = wm + (lane >> 2);
            uint32_t af[2][4], bfr[8][2];
#pragma unroll
            for (int mi = 0; mi < 2; mi++) {
                af[mi][0] = *(uint32_t*)&sA[cur][arow + mi * 16][acol];
                af[mi][1] = *(uint32_t*)&sA[cur][arow + mi * 16 + 8][acol];
                af[mi][2] = *(uint32_t*)&sA[cur][arow + mi * 16][acol + 8];
                af[mi][3] = *(uint32_t*)&sA[cur][arow + mi * 16 + 8][acol + 8];
            }
#pragma unroll
            for (int ni = 0; ni < 8; ni++) {
                bfr[ni][0] = *(uint32_t*)&sW[cur][wn + ni * 8 + (lane >> 2)][acol];
                bfr[ni][1] = *(uint32_t*)&sW[cur][wn + ni * 8 + (lane >> 2)][acol + 8];
            }
#pragma unroll
            for (int mi = 0; mi < 2; mi++)
#pragma unroll
                for (int ni = 0; ni < 8; ni++)
                    asm volatile(
                        "mma.sync.aligned.m16n8k16.row.col.f32.bf16.bf16.f32 "
                        "{%0,%1,%2,%3}, {%4,%5,%6,%7}, {%8,%9}, {%0,%1,%2,%3};"
                        : "+f"(acc[mi][ni][0]), "+f"(acc[mi][ni][1]),
                          "+f"(acc[mi][ni][2]), "+f"(acc[mi][ni][3])
                        : "r"(af[mi][0]), "r"(af[mi][1]), "r"(af[mi][2]), "r"(af[mi][3]),
                          "r"(bfr[ni][0]), "r"(bfr[ni][1]));
        }
        __syncthreads();
        if (s + 1 < nsteps) {
            *(uint4*)&sA[cur ^ 1][lr][lc] = ra0; *(uint4*)&sA[cur ^ 1][lr][lc + 8] = ra1;
            *(uint4*)&sW[cur ^ 1][lr][lc] = rw0; *(uint4*)&sW[cur ^ 1][lr][lc + 8] = rw1;
        }
        __syncthreads();
    }
    const int r0 = lane >> 2, c0 = (lane & 3) * 2;
#pragma unroll
    for (int mi = 0; mi < 2; mi++)
#pragma unroll
        for (int ni = 0; ni < 8; ni++) {
            int gr = m0 + wm + mi * 16 + r0;
            int gc = wn + ni * 8 + c0;
            float v0 = acc[mi][ni][0], v1 = acc[mi][ni][1];
            float v2 = acc[mi][ni][2], v3 = acc[mi][ni][3];
            int gcg = n0 + gc;
            if (bias) {
                float2 bb = *(const float2*)&bias[gcg];
                v0 += bb.x; v1 += bb.y; v2 += bb.x; v3 += bb.y;
            }
            if (addm) {
                float2 a0 = *(const float2*)&addm[(size_t)gr * addld + gcg];
                float2 a1 = *(const float2*)&addm[(size_t)(gr + 8) * addld + gcg];
                v0 += a0.x; v1 += a0.y; v2 += a1.x; v3 += a1.y;
            }
            *(float2*)&C[(size_t)gr * ldc + gcg] = make_float2(v0, v1);
            *(float2*)&C[(size_t)(gr + 8) * ldc + gcg] = make_float2(v2, v3);
        }
}

// ---------------- hierarchical grid barrier ----------------
// 8 group counters (16 blocks each) -> root (8) -> epoch flag.
__device__ __forceinline__ void gbar(unsigned n) {
    __syncthreads();
    if (threadIdx.x == 0) {
        __threadfence();
        unsigned g = blockIdx.x & 7;
        unsigned prev = atomicAdd(&g_cntG[g * 32], 1u);
        if (prev == n * 16 - 1) {
            unsigned pr = atomicAdd(&g_cntR, 1u);
            if (pr == n * 8 - 1) {
                g_epoch = n;
                __threadfence();
            }
        }
        while (g_epoch < n) { }
    }
    __syncthreads();
}

// ---------------- persistent recurrent loop (R6 structure + fused At3 logging) ----
__global__ void __launch_bounds__(256, 1) loop_kernel(const float* __restrict__ Wm1,
                                                      const float* __restrict__ W12,
                                                      const float* __restrict__ Wm2,
                                                      float* __restrict__ out) {
    __shared__ float sIn[64 * 64];
    __shared__ float sWA[32 * 64];
    __shared__ float sWB[64 * 16];
    __shared__ float sWC[32 * 8];

    const int tid = threadIdx.x, blk = blockIdx.x;
    const int ht = blk >> 3, mcc = blk & 7;
    const int otile = blk >> 4, kc = blk & 15;
    const int hy = tid >> 4, bx = tid & 15;
    const int oy = tid >> 5, b2 = tid & 31;

    for (int i = tid; i < 32 * 64; i += 256) {
        int m = i >> 6, h = i & 63;
        sWA[i] = Wm1[(ht * 64 + h) * 256 + mcc * 32 + m];
    }
    for (int i = tid; i < 64 * 16; i += 256) {
        int k = i >> 4, o = i & 15;
        sWB[i] = W12[(otile * 16 + o) * 1024 + kc * 64 + k];
    }
    for (int i = tid; i < 32 * 8; i += 256) {
        int m = i >> 3, o = i & 7;
        sWC[i] = Wm2[(ht * 8 + o) * 256 + mcc * 32 + m];
    }
    __syncthreads();

    unsigned bn = 1;
    for (int t = 0; t < NT; t++) {
        const int par = t & 1, nxt = par ^ 1;
        for (int i = tid; i < 512; i += 256) {
            int m = i >> 4, b4 = (i & 15) * 4;
            *(float4*)&sIn[m * 64 + b4] = __ldcg((const float4*)&g_memT[par][(mcc * 32 + m) * 64 + b4]);
        }
        __syncthreads();
        {
            float acc[4][4] = {};
#pragma unroll 8
            for (int m = 0; m < 32; m++) {
                float4 w = *(float4*)&sWA[m * 64 + hy * 4];
                float4 x = *(float4*)&sIn[m * 64 + bx * 4];
                acc[0][0] += w.x * x.x; acc[0][1] += w.x * x.y; acc[0][2] += w.x * x.z; acc[0][3] += w.x * x.w;
                acc[1][0] += w.y * x.x; acc[1][1] += w.y * x.y; acc[1][2] += w.y * x.z; acc[1][3] += w.y * x.w;
                acc[2][0] += w.z * x.x; acc[2][1] += w.z * x.y; acc[2][2] += w.z * x.z; acc[2][3] += w.z * x.w;
                acc[3][0] += w.w * x.x; acc[3][1] += w.w * x.y; acc[3][2] += w.w * x.z; acc[3][3] += w.w * x.w;
            }
#pragma unroll
            for (int i = 0; i < 4; i++)
                __stcg((float4*)&g_Apart[(mcc * 1024 + ht * 64 + hy * 4 + i) * 64 + bx * 4],
                       make_float4(acc[i][0], acc[i][1], acc[i][2], acc[i][3]));
        }
        {
            int b = tid & 63, og = (tid >> 6) * 2;
            float a0 = 0.f, a1 = 0.f;
#pragma unroll 8
            for (int m = 0; m < 32; m++) {
                float x = sIn[m * 64 + b];
                a0 += sWC[m * 8 + og] * x;
                a1 += sWC[m * 8 + og + 1] * x;
            }
            __stcg(&g_Bpart[((16 + mcc) * 128 + ht * 8 + og) * 64 + b], a0);
            __stcg(&g_Bpart[((16 + mcc) * 128 + ht * 8 + og + 1) * 64 + b], a1);
        }
        gbar(bn++);
        // ===== R1: reduce partials + pre1, act, write v1T/memT-head/At3 =====
        {
            int b = tid >> 2, h0 = blk * 8 + (tid & 3) * 2;
            int row = b * NT + t;
            float2 p = __ldcg((const float2*)&g_pre1[(size_t)row * 1024 + h0]);
            float s0 = p.x, s1 = p.y;
#pragma unroll
            for (int mc = 0; mc < 8; mc++) {
                s0 += __ldcg(&g_Apart[(mc * 1024 + h0) * 64 + b]);
                s1 += __ldcg(&g_Apart[(mc * 1024 + h0 + 1) * 64 + b]);
            }
            if (h0 < 512) { s0 = tanhf(s0); s1 = tanhf(s1); }
            else { s0 = fmaxf(s0, 0.f); s1 = fmaxf(s1, 0.f); }
            __stcg(&g_v1T[h0 * 64 + b], s0);
            __stcg(&g_v1T[(h0 + 1) * 64 + b], s1);
            __nv_bfloat162 hh, ll;
            hh.x = __float2bfloat16(s0); hh.y = __float2bfloat16(s1);
            ll.x = __float2bfloat16(s0 - __bfloat162float(hh.x));
            ll.y = __float2bfloat16(s1 - __bfloat162float(hh.y));
            size_t base = (size_t)row * 3840;
            *(__nv_bfloat162*)&g_At3[base + h0] = hh;
            *(__nv_bfloat162*)&g_At3[base + 1280 + h0] = hh;
            *(__nv_bfloat162*)&g_At3[base + 2560 + h0] = ll;
            if (h0 < 128) {
                __stcg(&g_memT[nxt][h0 * 64 + b], s0);
                __stcg(&g_memT[nxt][(h0 + 1) * 64 + b], s1);
                if (t + 1 < NT) {
                    size_t b2a = (size_t)(row + 1) * 3840;
                    *(__nv_bfloat162*)&g_At3[b2a + 1024 + h0] = hh;
                    *(__nv_bfloat162*)&g_At3[b2a + 2304 + h0] = hh;
                    *(__nv_bfloat162*)&g_At3[b2a + 3584 + h0] = ll;
                }
            }
        }
        gbar(bn++);
        // ===== Phase B: v1 -> v2head partials =====
        for (int i = tid; i < 1024; i += 256) {
            int k = i >> 4, b4 = (i & 15) * 4;
            *(float4*)&sIn[k * 64 + b4] = __ldcg((const float4*)&g_v1T[(kc * 64 + k) * 64 + b4]);
        }
        __syncthreads();
        {
            float a00 = 0.f, a01 = 0.f, a10 = 0.f, a11 = 0.f;
#pragma unroll 8
            for (int k = 0; k < 64; k++) {
                float2 w = *(float2*)&sWB[k * 16 + oy * 2];
                float2 x = *(float2*)&sIn[k * 64 + b2 * 2];
                a00 += w.x * x.x; a01 += w.x * x.y;
                a10 += w.y * x.x; a11 += w.y * x.y;
            }
            int ob = (kc * 128 + otile * 16 + oy * 2) * 64 + b2 * 2;
            __stcg(&g_Bpart[ob], a00);       __stcg(&g_Bpart[ob + 1], a01);
            __stcg(&g_Bpart[ob + 64], a10);  __stcg(&g_Bpart[ob + 65], a11);
        }
        gbar(bn++);
        // ===== R2: reduce 24 partials + pre2, sigmoid, out/memT-tail/At3 =====
        if (tid < 64) {
            int o = blk, b = tid;
            int row = b * NT + t;
            float s = __ldcg(&g_pre2[(size_t)row * 512 + o]);
#pragma unroll
            for (int p = 0; p < 24; p++) s += __ldcg(&g_Bpart[(p * 128 + o) * 64 + b]);
            s = 1.f / (1.f + expf(-s));
            __stcg(&out[(size_t)row * 512 + o], s);
            __stcg(&g_memT[nxt][(128 + o) * 64 + b], s);
            if (t + 1 < NT) {
                __nv_bfloat16 h = __float2bfloat16(s);
                __nv_bfloat16 l = __float2bfloat16(s - __bfloat162float(h));
                size_t b2a = (size_t)(row + 1) * 3840;
                g_At3[b2a + 1152 + o] = h;
                g_At3[b2a + 2432 + o] = h;
                g_At3[b2a + 3712 + o] = l;
            }
        }
        gbar(bn++);
    }
}

// ---------------- launch ----------------
extern "C" void kernel_launch(void* const* d_in, const int* in_sizes, int n_in,
                              void* d_out, int out_size) {
    const float* X   = (const float*)d_in[0];
    const float* mem = (const float*)d_in[1];
    const float* W01 = (const float*)d_in[2];
    const float* b01 = (const float*)d_in[3];
    const float* W02 = (const float*)d_in[4];
    const float* b02 = (const float*)d_in[5];
    const float* W12 = (const float*)d_in[6];
    const float* b12 = (const float*)d_in[7];
    const float* Wm1 = (const float*)d_in[8];
    const float* bm1 = (const float*)d_in[9];
    const float* Wm2 = (const float*)d_in[10];
    const float* bm2 = (const float*)d_in[11];
    float* out = (float*)d_out;

    float *pre1, *pre2, *b1, *b2;
    __nv_bfloat16 *X3, *W013, *W023, *Wt3, *At3;
    cudaGetSymbolAddress((void**)&pre1, g_pre1);
    cudaGetSymbolAddress((void**)&pre2, g_pre2);
    cudaGetSymbolAddress((void**)&b1, g_bias1);
    cudaGetSymbolAddress((void**)&b2, g_bias2);
    cudaGetSymbolAddress((void**)&X3, g_X3);
    cudaGetSymbolAddress((void**)&W013, g_W013);
    cudaGetSymbolAddress((void**)&W023, g_W023);
    cudaGetSymbolAddress((void**)&Wt3, g_Wt3);
    cudaGetSymbolAddress((void**)&At3, g_At3);

    prep_kernel<<<64, 256>>>(b01, bm1, b02, b12, bm2, mem);
    split3_kernel<<<2048, 256>>>(X, X3, 512, NROWS * 512, 1);
    split3_kernel<<<512, 256>>>(W01, W013, 512, 1024 * 512, 0);
    split3_kernel<<<256, 256>>>(W02, W023, 512, 512 * 512, 0);
    splitWtail_kernel<<<512, 256>>>(W12, Wm2);
    hgemm_kernel<<<dim3(8, 256), 256>>>(X3, W013, 1536, pre1, 1024, b1, nullptr, 0, 1);
    hgemm_kernel<<<dim3(4, 256), 256>>>(X3, W023, 1536, pre2, 512, b2, nullptr, 0, 1);
    loop_kernel<<<NB, 256>>>(Wm1, W12, Wm2, out);
    hgemm_kernel<<<dim3(3, 256), 256>>>(At3, Wt3, 3840, out + 128, 512,
                                        nullptr, pre2 + 128, 512, 1);
}

// round 9
// speedup vs baseline: 1.0506x; 1.0506x over previous
#include <cuda_runtime.h>
#include <cuda_bf16.h>
#include <cstdint>
#include <math.h>

#define NBATCH 64
#define NT     512
#define NROWS  (NBATCH * NT)

// ---------------- device scratch ----------------
__device__ float g_pre1[NROWS * 1024];
__device__ float g_pre2[NROWS * 512];
__device__ float g_v1all[NROWS * 1024];
__device__ float g_memall[NROWS * 256];
__device__ float g_v1T[1024 * 64];
__device__ float g_memT[2][256 * 64];
__device__ float g_Apart[8 * 1024 * 64];
__device__ float g_Bpart[24 * 128 * 64];
__device__ float g_bias1[1024];
__device__ float g_bias2[512];
__device__ unsigned g_barCnt;
// bf16 split operands (K-concat trick)
__device__ __nv_bfloat16 g_X3[NROWS * 1536];       // [Ah|Ah|Al]
__device__ __nv_bfloat16 g_W013[1024 * 1536];      // [Wh|Wl|Wh]
__device__ __nv_bfloat16 g_W023[512 * 1536];
__device__ __nv_bfloat16 g_Wt3[384 * 3840];
__device__ __nv_bfloat16 g_At3[NROWS * 3840];

// ---------------- prep ----------------
__global__ void prep_kernel(const float* __restrict__ b01, const float* __restrict__ bm1,
                            const float* __restrict__ b02, const float* __restrict__ b12,
                            const float* __restrict__ bm2, const float* __restrict__ memory) {
    int i = blockIdx.x * blockDim.x + threadIdx.x;
    int n = gridDim.x * blockDim.x;
    if (i == 0) g_barCnt = 0u;
    for (int j = i; j < 1024; j += n) g_bias1[j] = b01[j] + bm1[j];
    for (int j = i; j < 512; j += n) g_bias2[j] = b02[j] + b12[j] + bm2[j];
    for (int j = i; j < 256 * 64; j += n) {
        int m = j >> 6, b = j & 63;
        g_memT[0][j] = memory[b * 256 + m];
    }
}

// split fp32 -> bf16 hi/lo, K-concat. aMode: [h|h|l]  else (W): [h|l|h]
__global__ void split3_kernel(const float* __restrict__ src, __nv_bfloat16* __restrict__ dst,
                              int K, int total, int aMode) {
    for (int i = blockIdx.x * blockDim.x + threadIdx.x; i < total; i += gridDim.x * blockDim.x) {
        int r = i / K, k = i % K;
        float x = src[i];
        __nv_bfloat16 h = __float2bfloat16(x);
        __nv_bfloat16 l = __float2bfloat16(x - __bfloat162float(h));
        __nv_bfloat16* d = dst + (size_t)r * 3 * K + k;
        d[0] = h;
        d[K] = aMode ? h : l;
        d[2 * K] = aMode ? l : h;
    }
}

// tail W: rows o=0..383 map to W12[o+128], Wm2[o+128]; layout [Wh|Wl|Wh] over K=1280
__global__ void splitWtail_kernel(const float* __restrict__ W12, const float* __restrict__ Wm2) {
    for (int i = blockIdx.x * blockDim.x + threadIdx.x; i < 384 * 1280; i += gridDim.x * blockDim.x) {
        int o = i / 1280, k = i % 1280;
        float x = (k < 1024) ? W12[(o + 128) * 1024 + k] : Wm2[(o + 128) * 256 + (k - 1024)];
        __nv_bfloat16 h = __float2bfloat16(x);
        __nv_bfloat16 l = __float2bfloat16(x - __bfloat162float(h));
        __nv_bfloat16* d = g_Wt3 + (size_t)o * 3840 + k;
        d[0] = h; d[1280] = l; d[2560] = h;
    }
}

// tail A: [v1|mem] -> [Ah|Ah|Al] over K=1280
__global__ void tailA_kernel() {
    for (int i = blockIdx.x * blockDim.x + threadIdx.x; i < NROWS * 1280; i += gridDim.x * blockDim.x) {
        int r = i / 1280, k = i % 1280;
        float x = (k < 1024) ? g_v1all[(size_t)r * 1024 + k] : g_memall[(size_t)r * 256 + (k - 1024)];
        __nv_bfloat16 h = __float2bfloat16(x);
        __nv_bfloat16 l = __float2bfloat16(x - __bfloat162float(h));
        __nv_bfloat16* d = g_At3 + (size_t)r * 3840 + k;
        d[0] = h; d[1280] = h; d[2560] = l;
    }
}

// ---------------- bf16 tensor-core GEMM: C[m][n] = sum_k A[m][k]*W[n][k] (+bias/+addm) ----
__global__ void __launch_bounds__(256) hgemm_kernel(const __nv_bfloat16* __restrict__ A,
                                                    const __nv_bfloat16* __restrict__ W, int K,
                                                    float* __restrict__ C, int ldc,
                                                    const float* __restrict__ bias,
                                                    const float* __restrict__ addm, int addld) {
    __shared__ __nv_bfloat16 sA[2][128][40];
    __shared__ __nv_bfloat16 sW[2][128][40];
    const int tid = threadIdx.x;
    const int m0 = blockIdx.x * 128, n0 = blockIdx.y * 128;
    const int warp = tid >> 5, lane = tid & 31;
    const int wm = (warp >> 1) * 32, wn = (warp & 1) * 64;
    const int lr = tid >> 1, lc = (tid & 1) * 16;   // 2 threads/row, 16 bf16 each
    float acc[2][8][4] = {};
    const __nv_bfloat16* Ag = A + (size_t)(m0 + lr) * K + lc;
    const __nv_bfloat16* Wg = W + (size_t)(n0 + lr) * K + lc;
    uint4 ra0 = *(const uint4*)Ag, ra1 = *(const uint4*)(Ag + 8);
    uint4 rw0 = *(const uint4*)Wg, rw1 = *(const uint4*)(Wg + 8);
    *(uint4*)&sA[0][lr][lc] = ra0; *(uint4*)&sA[0][lr][lc + 8] = ra1;
    *(uint4*)&sW[0][lr][lc] = rw0; *(uint4*)&sW[0][lr][lc + 8] = rw1;
    __syncthreads();
    const int nsteps = K / 32;
    for (int s = 0; s < nsteps; s++) {
        const int cur = s & 1;
        if (s + 1 < nsteps) {
            const __nv_bfloat16* An = Ag + (size_t)(s + 1) * 32;
            const __nv_bfloat16* Wn = Wg + (size_t)(s + 1) * 32;
            ra0 = *(const uint4*)An; ra1 = *(const uint4*)(An + 8);
            rw0 = *(const uint4*)Wn; rw1 = *(const uint4*)(Wn + 8);
        }
#pragma unroll
        for (int kf = 0; kf < 2; kf++) {
            const int acol = kf * 16 + (lane & 3) * 2;
            const int arow = wm + (lane >> 2);
            uint32_t af[2][4], bfr[8][2];
#pragma unroll
            for (int mi = 0; mi < 2; mi++) {
                af[mi][0] = *(uint32_t*)&sA[cur][arow + mi * 16][acol];
                af[mi][1] = *(uint32_t*)&sA[cur][arow + mi * 16 + 8][acol];
                af[mi][2] = *(uint32_t*)&sA[cur][arow + mi * 16][acol + 8];
                af[mi][3] = *(uint32_t*)&sA[cur][arow + mi * 16 + 8][acol + 8];
            }
#pragma unroll
            for (int ni = 0; ni < 8; ni++) {
                bfr[ni][0] = *(uint32_t*)&sW[cur][wn + ni * 8 + (lane >> 2)][acol];
                bfr[ni][1] = *(uint32_t*)&sW[cur][wn + ni * 8 + (lane >> 2)][acol + 8];
            }
#pragma unroll
            for (int mi = 0; mi < 2; mi++)
#pragma unroll
                for (int ni = 0; ni < 8; ni++)
                    asm volatile(
                        "mma.sync.aligned.m16n8k16.row.col.f32.bf16.bf16.f32 "
                        "{%0,%1,%2,%3}, {%4,%5,%6,%7}, {%8,%9}, {%0,%1,%2,%3};"
                        : "+f"(acc[mi][ni][0]), "+f"(acc[mi][ni][1]),
                          "+f"(acc[mi][ni][2]), "+f"(acc[mi][ni][3])
                        : "r"(af[mi][0]), "r"(af[mi][1]), "r"(af[mi][2]), "r"(af[mi][3]),
                          "r"(bfr[ni][0]), "r"(bfr[ni][1]));
        }
        __syncthreads();
        if (s + 1 < nsteps) {
            *(uint4*)&sA[cur ^ 1][lr][lc] = ra0; *(uint4*)&sA[cur ^ 1][lr][lc + 8] = ra1;
            *(uint4*)&sW[cur ^ 1][lr][lc] = rw0; *(uint4*)&sW[cur ^ 1][lr][lc + 8] = rw1;
        }
        __syncthreads();
    }
    const int r0 = lane >> 2, c0 = (lane & 3) * 2;
#pragma unroll
    for (int mi = 0; mi < 2; mi++)
#pragma unroll
        for (int ni = 0; ni < 8; ni++) {
            int gr = m0 + wm + mi * 16 + r0;
            int gc = wn + ni * 8 + c0;
            float v0 = acc[mi][ni][0], v1 = acc[mi][ni][1];
            float v2 = acc[mi][ni][2], v3 = acc[mi][ni][3];
            int gcg = n0 + gc;
            if (bias) {
                float2 bb = *(const float2*)&bias[gcg];
                v0 += bb.x; v1 += bb.y; v2 += bb.x; v3 += bb.y;
            }
            if (addm) {
                float2 a0 = *(const float2*)&addm[(size_t)gr * addld + gcg];
                float2 a1 = *(const float2*)&addm[(size_t)(gr + 8) * addld + gcg];
                v0 += a0.x; v1 += a0.y; v2 += a1.x; v3 += a1.y;
            }
            *(float2*)&C[(size_t)gr * ldc + gcg] = make_float2(v0, v1);
            *(float2*)&C[(size_t)(gr + 8) * ldc + gcg] = make_float2(v2, v3);
        }
}

// ---------------- persistent recurrent loop: 512 threads/block (16 warps/SM) ----------------
__device__ __forceinline__ void gbar(unsigned target) {
    __syncthreads();
    if (threadIdx.x == 0) {
        __threadfence();
        atomicAdd(&g_barCnt, 1u);
        while (*(volatile unsigned*)&g_barCnt < target) { }
    }
    __syncthreads();
}

__global__ void __launch_bounds__(512, 1) loop_kernel(const float* __restrict__ Wm1,
                                                      const float* __restrict__ W12,
                                                      const float* __restrict__ Wm2,
                                                      float* __restrict__ out) {
    __shared__ float sIn[64 * 64];
    __shared__ float sWA[32 * 64];
    __shared__ float sWB[64 * 16];
    __shared__ float sWC[32 * 8];

    const int tid = threadIdx.x, blk = blockIdx.x;
    const int ht = blk >> 3, mcc = blk & 7;       // phase A: 16 h-tiles x 8 m-chunks
    const int otile = blk >> 4, kc = blk & 15;    // phase B: 8 o-tiles x 16 k-chunks
    const int hy = tid >> 4, bx = tid & 15;       // phase A: 32x16 threads, 2h x 4b each
    const int oy = tid >> 5, b2 = tid & 31;       // phase B: 16x32 threads, 1o x 2b each

    for (int i = tid; i < 32 * 64; i += 512) {
        int m = i >> 6, h = i & 63;
        sWA[i] = Wm1[(ht * 64 + h) * 256 + mcc * 32 + m];
    }
    for (int i = tid; i < 64 * 16; i += 512) {
        int k = i >> 4, o = i & 15;
        sWB[i] = W12[(otile * 16 + o) * 1024 + kc * 64 + k];
    }
    for (int i = tid; i < 32 * 8; i += 512) {
        int m = i >> 3, o = i & 7;
        sWC[i] = Wm2[(ht * 8 + o) * 256 + mcc * 32 + m];
    }
    __syncthreads();

    unsigned tgt = 128;
    for (int t = 0; t < NT; t++) {
        const int par = t & 1, nxt = par ^ 1;
        {   // stage mem slice [32m][64b]: 512 float4 = exactly one per thread
            int m = tid >> 4, b4 = (tid & 15) * 4;
            *(float4*)&sIn[m * 64 + b4] = __ldcg((const float4*)&g_memT[par][(mcc * 32 + m) * 64 + b4]);
        }
        __syncthreads();
        if (ht == 0) {
            for (int i = tid; i < 2048; i += 512) {
                int b = i >> 5, m = i & 31;
                __stcg(&g_memall[(b * NT + t) * 256 + mcc * 32 + m], sIn[m * 64 + b]);
            }
        }
        {   // phase A: 2h x 4b per thread over 32 m
            float acc[2][4] = {};
#pragma unroll 8
            for (int m = 0; m < 32; m++) {
                float2 w = *(float2*)&sWA[m * 64 + hy * 2];
                float4 x = *(float4*)&sIn[m * 64 + bx * 4];
                acc[0][0] += w.x * x.x; acc[0][1] += w.x * x.y; acc[0][2] += w.x * x.z; acc[0][3] += w.x * x.w;
                acc[1][0] += w.y * x.x; acc[1][1] += w.y * x.y; acc[1][2] += w.y * x.z; acc[1][3] += w.y * x.w;
            }
#pragma unroll
            for (int i = 0; i < 2; i++)
                __stcg((float4*)&g_Apart[(mcc * 1024 + ht * 64 + hy * 2 + i) * 64 + bx * 4],
                       make_float4(acc[i][0], acc[i][1], acc[i][2], acc[i][3]));
        }
        {   // v2head mem contribution: 8 o x 64 b, 1 each
            int b = tid & 63, og = tid >> 6;
            float a0 = 0.f;
#pragma unroll 8
            for (int m = 0; m < 32; m++) a0 += sWC[m * 8 + og] * sIn[m * 64 + b];
            __stcg(&g_Bpart[((16 + mcc) * 128 + ht * 8 + og) * 64 + b], a0);
        }
        gbar(tgt); tgt += 128;
        // ===== R1: reduce partials + pre1, act, write v1T/v1all/mem head =====
        {
            int b = tid >> 3, h0 = blk * 8 + (tid & 7);
            int row = b * NT + t;
            float s = __ldcg(&g_pre1[(size_t)row * 1024 + h0]);
#pragma unroll
            for (int mc = 0; mc < 8; mc++)
                s += __ldcg(&g_Apart[(mc * 1024 + h0) * 64 + b]);
            if (h0 < 512) s = tanhf(s);
            else s = fmaxf(s, 0.f);
            __stcg(&g_v1T[h0 * 64 + b], s);
            __stcg(&g_v1all[(size_t)row * 1024 + h0], s);
            if (h0 < 128) __stcg(&g_memT[nxt][h0 * 64 + b], s);
        }
        gbar(tgt); tgt += 128;
        // ===== Phase B: v1 -> v2head partials (o-tile 16, k-chunk 64) =====
        for (int i = tid; i < 1024; i += 512) {
            int k = i >> 4, b4 = (i & 15) * 4;
            *(float4*)&sIn[k * 64 + b4] = __ldcg((const float4*)&g_v1T[(kc * 64 + k) * 64 + b4]);
        }
        __syncthreads();
        {
            float a0 = 0.f, a1 = 0.f;
#pragma unroll 8
            for (int k = 0; k < 64; k++) {
                float w = sWB[k * 16 + oy];
                float2 x = *(float2*)&sIn[k * 64 + b2 * 2];
                a0 += w * x.x; a1 += w * x.y;
            }
            int ob = (kc * 128 + otile * 16 + oy) * 64 + b2 * 2;
            __stcg((float2*)&g_Bpart[ob], make_float2(a0, a1));
        }
        gbar(tgt); tgt += 128;
        // ===== R2: reduce 24 partials + pre2, sigmoid, write out head + mem tail =====
        if (tid < 64) {
            int o = blk, b = tid;
            int row = b * NT + t;
            float s = __ldcg(&g_pre2[(size_t)row * 512 + o]);
#pragma unroll
            for (int p = 0; p < 24; p++) s += __ldcg(&g_Bpart[(p * 128 + o) * 64 + b]);
            s = 1.f / (1.f + expf(-s));
            __stcg(&out[(size_t)row * 512 + o], s);
            __stcg(&g_memT[nxt][(128 + o) * 64 + b], s);
        }
        gbar(tgt); tgt += 128;
    }
}

// ---------------- launch ----------------
extern "C" void kernel_launch(void* const* d_in, const int* in_sizes, int n_in,
                              void* d_out, int out_size) {
    const float* X   = (const float*)d_in[0];
    const float* mem = (const float*)d_in[1];
    const float* W01 = (const float*)d_in[2];
    const float* b01 = (const float*)d_in[3];
    const float* W02 = (const float*)d_in[4];
    const float* b02 = (const float*)d_in[5];
    const float* W12 = (const float*)d_in[6];
    const float* b12 = (const float*)d_in[7];
    const float* Wm1 = (const float*)d_in[8];
    const float* bm1 = (const float*)d_in[9];
    const float* Wm2 = (const float*)d_in[10];
    const float* bm2 = (const float*)d_in[11];
    float* out = (float*)d_out;

    float *pre1, *pre2, *b1, *b2;
    __nv_bfloat16 *X3, *W013, *W023, *Wt3, *At3;
    cudaGetSymbolAddress((void**)&pre1, g_pre1);
    cudaGetSymbolAddress((void**)&pre2, g_pre2);
    cudaGetSymbolAddress((void**)&b1, g_bias1);
    cudaGetSymbolAddress((void**)&b2, g_bias2);
    cudaGetSymbolAddress((void**)&X3, g_X3);
    cudaGetSymbolAddress((void**)&W013, g_W013);
    cudaGetSymbolAddress((void**)&W023, g_W023);
    cudaGetSymbolAddress((void**)&Wt3, g_Wt3);
    cudaGetSymbolAddress((void**)&At3, g_At3);

    prep_kernel<<<32, 256>>>(b01, bm1, b02, b12, bm2, mem);
    split3_kernel<<<2048, 256>>>(X, X3, 512, NROWS * 512, 1);
    split3_kernel<<<512, 256>>>(W01, W013, 512, 1024 * 512, 0);
    split3_kernel<<<256, 256>>>(W02, W023, 512, 512 * 512, 0);
    splitWtail_kernel<<<512, 256>>>(W12, Wm2);
    hgemm_kernel<<<dim3(NROWS / 128, 8), 256>>>(X3, W013, 1536, pre1, 1024, b1, nullptr, 0);
    hgemm_kernel<<<dim3(NROWS / 128, 4), 256>>>(X3, W023, 1536, pre2, 512, b2, nullptr, 0);
    loop_kernel<<<128, 512>>>(Wm1, W12, Wm2, out);
    tailA_kernel<<<2048, 256>>>();
    hgemm_kernel<<<dim3(NROWS / 128, 3), 256>>>(At3, Wt3, 3840, out + 128, 512,
                                                nullptr, pre2 + 128, 512);
}

// round 10
// speedup vs baseline: 1.3856x; 1.3188x over previous
#include <cuda_runtime.h>
#include <cuda_bf16.h>
#include <cstdint>
#include <math.h>

#define NBATCH 64
#define NT     512
#define NROWS  (NBATCH * NT)
#define NGRP   8          // batch groups
#define GB     8          // batch per group
#define GBLK   16         // blocks per group

// ---------------- device scratch ----------------
__device__ float g_pre1[NROWS * 1024];
__device__ float g_pre2[NROWS * 512];
__device__ float g_v1all[NROWS * 1024];
__device__ float g_memall[NROWS * 256];
__device__ float g_v1T[1024 * 64];                 // [h][b] (only h<128 consumed in-loop)
__device__ float g_mem0T[256 * 64];                // initial memory [m][b]
__device__ float g_Apart[NGRP * 4 * 1024 * GB];    // [g][mc][h][bl]
__device__ float g_Bv[NGRP * 4 * 128 * GB];        // [g][kc][o][bl]
__device__ float g_Am[2][NGRP * 4 * 128 * GB];     // [par][g][mc][o][bl]
__device__ float g_bias1[1024];
__device__ float g_bias2[512];
__device__ unsigned g_cnt[NGRP * 32];              // per-group barrier counters, padded
// bf16 split operands (K-concat trick)
__device__ __nv_bfloat16 g_X3[NROWS * 1536];       // [Ah|Ah|Al]
__device__ __nv_bfloat16 g_W013[1024 * 1536];      // [Wh|Wl|Wh]
__device__ __nv_bfloat16 g_W023[512 * 1536];
__device__ __nv_bfloat16 g_Wt3[384 * 3840];
__device__ __nv_bfloat16 g_At3[NROWS * 3840];

// ---------------- prep ----------------
__global__ void prep_kernel(const float* __restrict__ b01, const float* __restrict__ bm1,
                            const float* __restrict__ b02, const float* __restrict__ b12,
                            const float* __restrict__ bm2, const float* __restrict__ memory) {
    int i = blockIdx.x * blockDim.x + threadIdx.x;
    int n = gridDim.x * blockDim.x;
    if (i < NGRP) g_cnt[i * 32] = 0u;
    for (int j = i; j < 1024; j += n) g_bias1[j] = b01[j] + bm1[j];
    for (int j = i; j < 512; j += n) g_bias2[j] = b02[j] + b12[j] + bm2[j];
    for (int j = i; j < 256 * 64; j += n) {
        int m = j >> 6, b = j & 63;
        g_mem0T[j] = memory[b * 256 + m];
    }
}

// split fp32 -> bf16 hi/lo, K-concat. aMode: [h|h|l]  else (W): [h|l|h]
__global__ void split3_kernel(const float* __restrict__ src, __nv_bfloat16* __restrict__ dst,
                              int K, int total, int aMode) {
    for (int i = blockIdx.x * blockDim.x + threadIdx.x; i < total; i += gridDim.x * blockDim.x) {
        int r = i / K, k = i % K;
        float x = src[i];
        __nv_bfloat16 h = __float2bfloat16(x);
        __nv_bfloat16 l = __float2bfloat16(x - __bfloat162float(h));
        __nv_bfloat16* d = dst + (size_t)r * 3 * K + k;
        d[0] = h;
        d[K] = aMode ? h : l;
        d[2 * K] = aMode ? l : h;
    }
}

__global__ void splitWtail_kernel(const float* __restrict__ W12, const float* __restrict__ Wm2) {
    for (int i = blockIdx.x * blockDim.x + threadIdx.x; i < 384 * 1280; i += gridDim.x * blockDim.x) {
        int o = i / 1280, k = i % 1280;
        float x = (k < 1024) ? W12[(o + 128) * 1024 + k] : Wm2[(o + 128) * 256 + (k - 1024)];
        __nv_bfloat16 h = __float2bfloat16(x);
        __nv_bfloat16 l = __float2bfloat16(x - __bfloat162float(h));
        __nv_bfloat16* d = g_Wt3 + (size_t)o * 3840 + k;
        d[0] = h; d[1280] = l; d[2560] = h;
    }
}

__global__ void tailA_kernel() {
    for (int i = blockIdx.x * blockDim.x + threadIdx.x; i < NROWS * 1280; i += gridDim.x * blockDim.x) {
        int r = i / 1280, k = i % 1280;
        float x = (k < 1024) ? g_v1all[(size_t)r * 1024 + k] : g_memall[(size_t)r * 256 + (k - 1024)];
        __nv_bfloat16 h = __float2bfloat16(x);
        __nv_bfloat16 l = __float2bfloat16(x - __bfloat162float(h));
        __nv_bfloat16* d = g_At3 + (size_t)r * 3840 + k;
        d[0] = h; d[1280] = h; d[2560] = l;
    }
}

// ---------------- bf16 tensor-core GEMM (unchanged, passing) ----------------
__global__ void __launch_bounds__(256) hgemm_kernel(const __nv_bfloat16* __restrict__ A,
                                                    const __nv_bfloat16* __restrict__ W, int K,
                                                    float* __restrict__ C, int ldc,
                                                    const float* __restrict__ bias,
                                                    const float* __restrict__ addm, int addld) {
    __shared__ __nv_bfloat16 sA[2][128][40];
    __shared__ __nv_bfloat16 sW[2][128][40];
    const int tid = threadIdx.x;
    const int m0 = blockIdx.x * 128, n0 = blockIdx.y * 128;
    const int warp = tid >> 5, lane = tid & 31;
    const int wm = (warp >> 1) * 32, wn = (warp & 1) * 64;
    const int lr = tid >> 1, lc = (tid & 1) * 16;
    float acc[2][8][4] = {};
    const __nv_bfloat16* Ag = A + (size_t)(m0 + lr) * K + lc;
    const __nv_bfloat16* Wg = W + (size_t)(n0 + lr) * K + lc;
    uint4 ra0 = *(const uint4*)Ag, ra1 = *(const uint4*)(Ag + 8);
    uint4 rw0 = *(const uint4*)Wg, rw1 = *(const uint4*)(Wg + 8);
    *(uint4*)&sA[0][lr][lc] = ra0; *(uint4*)&sA[0][lr][lc + 8] = ra1;
    *(uint4*)&sW[0][lr][lc] = rw0; *(uint4*)&sW[0][lr][lc + 8] = rw1;
    __syncthreads();
    const int nsteps = K / 32;
    for (int s = 0; s < nsteps; s++) {
        const int cur = s & 1;
        if (s + 1 < nsteps) {
            const __nv_bfloat16* An = Ag + (size_t)(s + 1) * 32;
            const __nv_bfloat16* Wn = Wg + (size_t)(s + 1) * 32;
            ra0 = *(const uint4*)An; ra1 = *(const uint4*)(An + 8);
            rw0 = *(const uint4*)Wn; rw1 = *(const uint4*)(Wn + 8);
        }
#pragma unroll
        for (int kf = 0; kf < 2; kf++) {
            const int acol = kf * 16 + (lane & 3) * 2;
            const int arow = wm + (lane >> 2);
            uint32_t af[2][4], bfr[8][2];
#pragma unroll
            for (int mi = 0; mi < 2; mi++) {
                af[mi][0] = *(uint32_t*)&sA[cur][arow + mi * 16][acol];
                af[mi][1] = *(uint32_t*)&sA[cur][arow + mi * 16 + 8][acol];
                af[mi][2] = *(uint32_t*)&sA[cur][arow + mi * 16][acol + 8];
                af[mi][3] = *(uint32_t*)&sA[cur][arow + mi * 16 + 8][acol + 8];
            }
#pragma unroll
            for (int ni = 0; ni < 8; ni++) {
                bfr[ni][0] = *(uint32_t*)&sW[cur][wn + ni * 8 + (lane >> 2)][acol];
                bfr[ni][1] = *(uint32_t*)&sW[cur][wn + ni * 8 + (lane >> 2)][acol + 8];
            }
#pragma unroll
            for (int mi = 0; mi < 2; mi++)
#pragma unroll
                for (int ni = 0; ni < 8; ni++)
                    asm volatile(
                        "mma.sync.aligned.m16n8k16.row.col.f32.bf16.bf16.f32 "
                        "{%0,%1,%2,%3}, {%4,%5,%6,%7}, {%8,%9}, {%0,%1,%2,%3};"
                        : "+f"(acc[mi][ni][0]), "+f"(acc[mi][ni][1]),
                          "+f"(acc[mi][ni][2]), "+f"(acc[mi][ni][3])
                        : "r"(af[mi][0]), "r"(af[mi][1]), "r"(af[mi][2]), "r"(af[mi][3]),
                          "r"(bfr[ni][0]), "r"(bfr[ni][1]));
        }
        __syncthreads();
        if (s + 1 < nsteps) {
            *(uint4*)&sA[cur ^ 1][lr][lc] = ra0; *(uint4*)&sA[cur ^ 1][lr][lc + 8] = ra1;
            *(uint4*)&sW[cur ^ 1][lr][lc] = rw0; *(uint4*)&sW[cur ^ 1][lr][lc + 8] = rw1;
        }
        __syncthreads();
    }
    const int r0 = lane >> 2, c0 = (lane & 3) * 2;
#pragma unroll
    for (int mi = 0; mi < 2; mi++)
#pragma unroll
        for (int ni = 0; ni < 8; ni++) {
            int gr = m0 + wm + mi * 16 + r0;
            int gc = wn + ni * 8 + c0;
            float v0 = acc[mi][ni][0], v1 = acc[mi][ni][1];
            float v2 = acc[mi][ni][2], v3 = acc[mi][ni][3];
            int gcg = n0 + gc;
            if (bias) {
                float2 bb = *(const float2*)&bias[gcg];
                v0 += bb.x; v1 += bb.y; v2 += bb.x; v3 += bb.y;
            }
            if (addm) {
                float2 a0 = *(const float2*)&addm[(size_t)gr * addld + gcg];
                float2 a1 = *(const float2*)&addm[(size_t)(gr + 8) * addld + gcg];
                v0 += a0.x; v1 += a0.y; v2 += a1.x; v3 += a1.y;
            }
            *(float2*)&C[(size_t)gr * ldc + gcg] = make_float2(v0, v1);
            *(float2*)&C[(size_t)(gr + 8) * ldc + gcg] = make_float2(v2, v3);
        }
}

// ---------------- batch-grouped persistent loop: 8 groups x 16 blocks ----------------
// smem layout (floats)
#define SWA   0          // [64m][256h]   Wm1 slice          16384
#define SWC   16384      // [64m][32o]    Wm2-head slice      2048
#define SX    18432      // [64m][8b]     mem slice            512
#define SV    18944      // [256h][8b]    v1 chunk            2048
#define SRED  20992      // [8w][32o][9]  Bv partial reduce   2304
#define STOT  23296

__global__ void __launch_bounds__(256, 1) loop_kernel(const float* __restrict__ Wm1,
                                                      const float* __restrict__ W12,
                                                      const float* __restrict__ Wm2,
                                                      float* __restrict__ out) {
    extern __shared__ float sm[];
    float* sWA = sm + SWA;
    float* sWC = sm + SWC;
    float* sX  = sm + SX;
    float* sV  = sm + SV;
    float* sRd = sm + SRED;

    const int tid = threadIdx.x;
    const int g   = blockIdx.x >> 4;            // group
    const int j   = blockIdx.x & 15;            // role within group
    const int ht  = j >> 2, mc = j & 3;         // P1 role: h-tile(256), m-chunk(64)
    const int ot  = j >> 2, kc = j & 3;         // P2 role: o-tile(32), k-chunk(256)
    const int B0  = g * GB;

    // --- one-time weight staging ---
    for (int i = tid; i < 64 * 256; i += 256) {
        int ml = i >> 8, hl = i & 255;
        sWA[ml * 256 + hl] = Wm1[(ht * 256 + hl) * 256 + mc * 64 + ml];
    }
    for (int i = tid; i < 64 * 32; i += 256) {
        int ml = i >> 5, oy = i & 31;
        sWC[ml * 32 + oy] = Wm2[(ht * 32 + oy) * 256 + mc * 64 + ml];
    }
    // P2 register-resident W12 slice: warp w -> k-subchunk, lane -> o
    const int warp = tid >> 5, lane = tid & 31;
    float wreg[32];
    {
        int o = ot * 32 + lane;
#pragma unroll
        for (int kk = 0; kk < 32; kk++)
            wreg[kk] = W12[o * 1024 + kc * 256 + warp * 32 + kk];
    }
    __syncthreads();

    // thread mappings
    const int hy = tid >> 1, bq = tid & 1;          // P1 compute: 2h x 4b
    const int oy = tid & 31, bi = tid >> 5;         // Am / Bv-reduce: 1o x 1b
    const int bl2 = tid & 7, hq = tid >> 3;         // P2 assembly: 8h x 1b

    unsigned tgt = GBLK;
    unsigned* cnt = &g_cnt[g * 32];

    for (int t = 0; t < NT; t++) {
        const int par0 = t & 1, par1 = par0 ^ 1;    // write parity, read parity (t-1)
        // ===== P1: assemble mem slice =====
        if (t == 0) {
#pragma unroll
            for (int i = 0; i < 2; i++) {
                int v = tid * 2 + i, ml = v >> 3, bl = v & 7;
                sX[ml * 8 + bl] = g_mem0T[(mc * 64 + ml) * 64 + B0 + bl];
            }
        } else if (mc < 2) {
#pragma unroll
            for (int i = 0; i < 2; i++) {
                int v = tid * 2 + i, ml = v >> 3, bl = v & 7;
                sX[ml * 8 + bl] = __ldcg(&g_v1T[(mc * 64 + ml) * 64 + B0 + bl]);
            }
        } else {
#pragma unroll
            for (int i = 0; i < 2; i++) {
                int v = tid * 2 + i, ml = v >> 3, bl = v & 7;
                int o = mc * 64 + ml - 128;
                int b = B0 + bl;
                float s = g_pre2[(size_t)(b * NT + t - 1) * 512 + o];
#pragma unroll
                for (int q = 0; q < 4; q++) {
                    s += __ldcg(&g_Am[par1][(((g * 4 + q) * 128) + o) * 8 + bl]);
                    s += __ldcg(&g_Bv[(((g * 4 + q) * 128) + o) * 8 + bl]);
                }
                s = 1.f / (1.f + expf(-s));
                sX[ml * 8 + bl] = s;
                if (ht == 0) __stcg(&out[(size_t)(b * NT + t - 1) * 512 + o], s);
            }
        }
        __syncthreads();
        if (ht == 0) {
#pragma unroll
            for (int i = 0; i < 2; i++) {
                int v = tid * 2 + i, ml = v >> 3, bl = v & 7;
                __stcg(&g_memall[(size_t)((B0 + bl) * NT + t) * 256 + mc * 64 + ml],
                       sX[ml * 8 + bl]);
            }
        }
        // ===== P1 compute: Apart (256h x 8b over 64m) =====
        {
            float acc[2][4] = {};
#pragma unroll 16
            for (int m = 0; m < 64; m++) {
                float2 w = *(float2*)&sWA[m * 256 + hy * 2];
                float4 x = *(float4*)&sX[m * 8 + bq * 4];
                acc[0][0] += w.x * x.x; acc[0][1] += w.x * x.y; acc[0][2] += w.x * x.z; acc[0][3] += w.x * x.w;
                acc[1][0] += w.y * x.x; acc[1][1] += w.y * x.y; acc[1][2] += w.y * x.z; acc[1][3] += w.y * x.w;
            }
#pragma unroll
            for (int r = 0; r < 2; r++) {
                int hg = ht * 256 + hy * 2 + r;
                __stcg((float4*)&g_Apart[((g * 4 + mc) * 1024 + hg) * 8 + bq * 4],
                       make_float4(acc[r][0], acc[r][1], acc[r][2], acc[r][3]));
            }
        }
        // ===== P1 compute: Am (32o x 8b over 64m) =====
        {
            float a = 0.f;
#pragma unroll 16
            for (int m = 0; m < 64; m++) a += sWC[m * 32 + oy] * sX[m * 8 + bi];
            __stcg(&g_Am[par0][((g * 4 + mc) * 128 + ht * 32 + oy) * 8 + bi], a);
        }
        // barrier 1
        __syncthreads();
        if (tid == 0) {
            __threadfence();
            atomicAdd(cnt, 1u);
            while (*(volatile unsigned*)cnt < tgt) { }
        }
        __syncthreads();
        tgt += GBLK;

        // ===== P2: assemble v1 chunk (256h x 8b) =====
        {
            const int b = B0 + bl2;
            const size_t prow = (size_t)(b * NT + t) * 1024 + kc * 256;
            const bool isTanh = (kc < 2);
#pragma unroll
            for (int i = 0; i < 8; i++) {
                int hl = hq * 8 + i;
                float s = g_pre1[prow + hl];
#pragma unroll
                for (int q = 0; q < 4; q++)
                    s += __ldcg(&g_Apart[((g * 4 + q) * 1024 + kc * 256 + hl) * 8 + bl2]);
                s = isTanh ? tanhf(s) : fmaxf(s, 0.f);
                sV[hl * 8 + bl2] = s;
                if (ot == 0) {
                    __stcg(&g_v1all[prow + hl], s);
                    if (kc == 0 && hl < 128) __stcg(&g_v1T[(kc * 256 + hl) * 64 + b], s);
                }
            }
        }
        __syncthreads();
        // ===== P2 compute: Bv (32o x 8b over own 32k via register weights) =====
        {
            float a8[8] = {};
#pragma unroll
            for (int kk = 0; kk < 32; kk++) {
                int hl = warp * 32 + kk;
                float w = wreg[kk];
#pragma unroll
                for (int b = 0; b < 8; b++) a8[b] += w * sV[hl * 8 + b];
            }
#pragma unroll
            for (int b = 0; b < 8; b++) sRd[(warp * 32 + lane) * 9 + b] = a8[b];
        }
        __syncthreads();
        {
            float s = 0.f;
#pragma unroll
            for (int w = 0; w < 8; w++) s += sRd[(w * 32 + oy) * 9 + bi];
            __stcg(&g_Bv[((g * 4 + kc) * 128 + ot * 32 + oy) * 8 + bi], s);
        }
        // barrier 2
        __syncthreads();
        if (tid == 0) {
            __threadfence();
            atomicAdd(cnt, 1u);
            while (*(volatile unsigned*)cnt < tgt) { }
        }
        __syncthreads();
        tgt += GBLK;
    }

    // ===== epilogue: out head for t = NT-1 =====
    if (mc >= 2 && ht == 0) {
#pragma unroll
        for (int i = 0; i < 2; i++) {
            int v = tid * 2 + i, ml = v >> 3, bl = v & 7;
            int o = mc * 64 + ml - 128;
            int b = B0 + bl;
            float s = g_pre2[(size_t)(b * NT + NT - 1) * 512 + o];
#pragma unroll
            for (int q = 0; q < 4; q++) {
                s += __ldcg(&g_Am[(NT - 1) & 1][(((g * 4 + q) * 128) + o) * 8 + bl]);
                s += __ldcg(&g_Bv[(((g * 4 + q) * 128) + o) * 8 + bl]);
            }
            s = 1.f / (1.f + expf(-s));
            __stcg(&out[(size_t)(b * NT + NT - 1) * 512 + o], s);
        }
    }
}

// ---------------- launch ----------------
extern "C" void kernel_launch(void* const* d_in, const int* in_sizes, int n_in,
                              void* d_out, int out_size) {
    const float* X   = (const float*)d_in[0];
    const float* mem = (const float*)d_in[1];
    const float* W01 = (const float*)d_in[2];
    const float* b01 = (const float*)d_in[3];
    const float* W02 = (const float*)d_in[4];
    const float* b02 = (const float*)d_in[5];
    const float* W12 = (const float*)d_in[6];
    const float* b12 = (const float*)d_in[7];
    const float* Wm1 = (const float*)d_in[8];
    const float* bm1 = (const float*)d_in[9];
    const float* Wm2 = (const float*)d_in[10];
    const float* bm2 = (const float*)d_in[11];
    float* out = (float*)d_out;

    float *pre1, *pre2, *b1, *b2;
    __nv_bfloat16 *X3, *W013, *W023, *Wt3, *At3;
    cudaGetSymbolAddress((void**)&pre1, g_pre1);
    cudaGetSymbolAddress((void**)&pre2, g_pre2);
    cudaGetSymbolAddress((void**)&b1, g_bias1);
    cudaGetSymbolAddress((void**)&b2, g_bias2);
    cudaGetSymbolAddress((void**)&X3, g_X3);
    cudaGetSymbolAddress((void**)&W013, g_W013);
    cudaGetSymbolAddress((void**)&W023, g_W023);
    cudaGetSymbolAddress((void**)&Wt3, g_Wt3);
    cudaGetSymbolAddress((void**)&At3, g_At3);

    static int smemSet = 0;
    if (!smemSet) {
        cudaFuncSetAttribute(loop_kernel, cudaFuncAttributeMaxDynamicSharedMemorySize,
                             STOT * sizeof(float));
        smemSet = 1;
    }

    prep_kernel<<<32, 256>>>(b01, bm1, b02, b12, bm2, mem);
    split3_kernel<<<2048, 256>>>(X, X3, 512, NROWS * 512, 1);
    split3_kernel<<<512, 256>>>(W01, W013, 512, 1024 * 512, 0);
    split3_kernel<<<256, 256>>>(W02, W023, 512, 512 * 512, 0);
    splitWtail_kernel<<<512, 256>>>(W12, Wm2);
    hgemm_kernel<<<dim3(NROWS / 128, 8), 256>>>(X3, W013, 1536, pre1, 1024, b1, nullptr, 0);
    hgemm_kernel<<<dim3(NROWS / 128, 4), 256>>>(X3, W023, 1536, pre2, 512, b2, nullptr, 0);
    loop_kernel<<<NGRP * GBLK, 256, STOT * sizeof(float)>>>(Wm1, W12, Wm2, out);
    tailA_kernel<<<2048, 256>>>();
    hgemm_kernel<<<dim3(NROWS / 128, 3), 256>>>(At3, Wt3, 3840, out + 128, 512,
                                                nullptr, pre2 + 128, 512);
}

// round 11
// speedup vs baseline: 1.4033x; 1.0128x over previous
#include <cuda_runtime.h>
#include <cuda_bf16.h>
#include <cstdint>
#include <math.h>

#define NBATCH 64
#define NT     512
#define NROWS  (NBATCH * NT)
#define NGRP   8          // batch groups
#define GB     8          // batch per group
#define GBLK   16         // blocks per group

// ---------------- device scratch ----------------
__device__ float g_pre1[NROWS * 1024];
__device__ float g_pre2[NROWS * 512];
__device__ float g_v1T[1024 * 64];                 // [h][b] (only h<128 consumed in-loop)
__device__ float g_mem0T[256 * 64];                // initial memory [m][b]
__device__ float g_Apart[NGRP * 4 * 1024 * GB];    // [g][mc][h][bl]
__device__ float g_Bv[NGRP * 4 * 128 * GB];        // [g][kc][o][bl]
__device__ float g_Am[2][NGRP * 4 * 128 * GB];     // [par][g][mc][o][bl]
__device__ float g_bias1[1024];
__device__ float g_bias2[512];
__device__ unsigned g_cnt[NGRP * 32];              // per-group barrier counters, padded
// bf16 split operands (K-concat trick)
__device__ __nv_bfloat16 g_X3[NROWS * 1536];       // [Ah|Ah|Al]
__device__ __nv_bfloat16 g_W013[1024 * 1536];      // [Wh|Wl|Wh]
__device__ __nv_bfloat16 g_W023[512 * 1536];
__device__ __nv_bfloat16 g_Wt3[384 * 3840];
__device__ __nv_bfloat16 g_At3[NROWS * 3840];      // filled by the loop

__device__ __forceinline__ float sigmoid_fast(float x) {
    return 1.f / (1.f + __expf(-x));
}
__device__ __forceinline__ float tanh_fast(float x) {
    float e = __expf(2.f * x);
    return 1.f - 2.f / (e + 1.f);
}

// ---------------- prep ----------------
__global__ void prep_kernel(const float* __restrict__ b01, const float* __restrict__ bm1,
                            const float* __restrict__ b02, const float* __restrict__ b12,
                            const float* __restrict__ bm2, const float* __restrict__ memory) {
    int i = blockIdx.x * blockDim.x + threadIdx.x;
    int n = gridDim.x * blockDim.x;
    if (i < NGRP) g_cnt[i * 32] = 0u;
    for (int j = i; j < 1024; j += n) g_bias1[j] = b01[j] + bm1[j];
    for (int j = i; j < 512; j += n) g_bias2[j] = b02[j] + b12[j] + bm2[j];
    for (int j = i; j < 256 * 64; j += n) {
        int m = j >> 6, b = j & 63;
        g_mem0T[j] = memory[b * 256 + m];
    }
}

// split fp32 -> bf16 hi/lo, K-concat. aMode: [h|h|l]  else (W): [h|l|h]
__global__ void split3_kernel(const float* __restrict__ src, __nv_bfloat16* __restrict__ dst,
                              int K, int total, int aMode) {
    for (int i = blockIdx.x * blockDim.x + threadIdx.x; i < total; i += gridDim.x * blockDim.x) {
        int r = i / K, k = i % K;
        float x = src[i];
        __nv_bfloat16 h = __float2bfloat16(x);
        __nv_bfloat16 l = __float2bfloat16(x - __bfloat162float(h));
        __nv_bfloat16* d = dst + (size_t)r * 3 * K + k;
        d[0] = h;
        d[K] = aMode ? h : l;
        d[2 * K] = aMode ? l : h;
    }
}

__global__ void splitWtail_kernel(const float* __restrict__ W12, const float* __restrict__ Wm2) {
    for (int i = blockIdx.x * blockDim.x + threadIdx.x; i < 384 * 1280; i += gridDim.x * blockDim.x) {
        int o = i / 1280, k = i % 1280;
        float x = (k < 1024) ? W12[(o + 128) * 1024 + k] : Wm2[(o + 128) * 256 + (k - 1024)];
        __nv_bfloat16 h = __float2bfloat16(x);
        __nv_bfloat16 l = __float2bfloat16(x - __bfloat162float(h));
        __nv_bfloat16* d = g_Wt3 + (size_t)o * 3840 + k;
        d[0] = h; d[1280] = l; d[2560] = h;
    }
}

// ---------------- bf16 tensor-core GEMM with 3-stage cp.async pipeline ----------------
#define STG 3

__device__ __forceinline__ void cp16(uint32_t s, const void* g) {
    asm volatile("cp.async.cg.shared.global [%0], [%1], 16;" :: "r"(s), "l"(g));
}

__global__ void __launch_bounds__(256) hgemm_kernel(const __nv_bfloat16* __restrict__ A,
                                                    const __nv_bfloat16* __restrict__ W, int K,
                                                    float* __restrict__ C, int ldc,
                                                    const float* __restrict__ bias,
                                                    const float* __restrict__ addm, int addld) {
    extern __shared__ __nv_bfloat16 hsm[];
    __nv_bfloat16 (*sA)[128][40] = (__nv_bfloat16(*)[128][40])hsm;
    __nv_bfloat16 (*sW)[128][40] = (__nv_bfloat16(*)[128][40])(hsm + STG * 128 * 40);
    const int tid = threadIdx.x;
    const int n0 = blockIdx.x * 128, m0 = blockIdx.y * 128;   // n fastest: A panel L2-reuse
    const int warp = tid >> 5, lane = tid & 31;
    const int wm = (warp >> 1) * 32, wn = (warp & 1) * 64;
    const int lr = tid >> 1, lc = (tid & 1) * 16;
    float acc[2][8][4] = {};
    const __nv_bfloat16* Ag = A + (size_t)(m0 + lr) * K + lc;
    const __nv_bfloat16* Wg = W + (size_t)(n0 + lr) * K + lc;
    uint32_t aAddr[STG], wAddr[STG];
#pragma unroll
    for (int s = 0; s < STG; s++) {
        aAddr[s] = (uint32_t)__cvta_generic_to_shared(&sA[s][lr][lc]);
        wAddr[s] = (uint32_t)__cvta_generic_to_shared(&sW[s][lr][lc]);
    }
    const int nsteps = K / 32;
#define HG_ISSUE(s) do { \
        int _st = (s) % STG; \
        const __nv_bfloat16* _ap = Ag + (size_t)(s) * 32; \
        const __nv_bfloat16* _wp = Wg + (size_t)(s) * 32; \
        cp16(aAddr[_st], _ap); cp16(aAddr[_st] + 16, _ap + 8); \
        cp16(wAddr[_st], _wp); cp16(wAddr[_st] + 16, _wp + 8); \
        asm volatile("cp.async.commit_group;"); \
    } while (0)
    HG_ISSUE(0);
    HG_ISSUE(1);
    asm volatile("cp.async.wait_group 1;");
    __syncthreads();
    for (int s = 0; s < nsteps; s++) {
        if (s + 2 < nsteps) HG_ISSUE(s + 2);
        const int cur = s % STG;
#pragma unroll
        for (int kf = 0; kf < 2; kf++) {
            const int acol = kf * 16 + (lane & 3) * 2;
            const int arow = wm + (lane >> 2);
            uint32_t af[2][4], bfr[8][2];
#pragma unroll
            for (int mi = 0; mi < 2; mi++) {
                af[mi][0] = *(uint32_t*)&sA[cur][arow + mi * 16][acol];
                af[mi][1] = *(uint32_t*)&sA[cur][arow + mi * 16 + 8][acol];
                af[mi][2] = *(uint32_t*)&sA[cur][arow + mi * 16][acol + 8];
                af[mi][3] = *(uint32_t*)&sA[cur][arow + mi * 16 + 8][acol + 8];
            }
#pragma unroll
            for (int ni = 0; ni < 8; ni++) {
                bfr[ni][0] = *(uint32_t*)&sW[cur][wn + ni * 8 + (lane >> 2)][acol];
                bfr[ni][1] = *(uint32_t*)&sW[cur][wn + ni * 8 + (lane >> 2)][acol + 8];
            }
#pragma unroll
            for (int mi = 0; mi < 2; mi++)
#pragma unroll
                for (int ni = 0; ni < 8; ni++)
                    asm volatile(
                        "mma.sync.aligned.m16n8k16.row.col.f32.bf16.bf16.f32 "
                        "{%0,%1,%2,%3}, {%4,%5,%6,%7}, {%8,%9}, {%0,%1,%2,%3};"
                        : "+f"(acc[mi][ni][0]), "+f"(acc[mi][ni][1]),
                          "+f"(acc[mi][ni][2]), "+f"(acc[mi][ni][3])
                        : "r"(af[mi][0]), "r"(af[mi][1]), "r"(af[mi][2]), "r"(af[mi][3]),
                          "r"(bfr[ni][0]), "r"(bfr[ni][1]));
        }
        asm volatile("cp.async.wait_group 1;");
        __syncthreads();
    }
    const int r0 = lane >> 2, c0 = (lane & 3) * 2;
#pragma unroll
    for (int mi = 0; mi < 2; mi++)
#pragma unroll
        for (int ni = 0; ni < 8; ni++) {
            int gr = m0 + wm + mi * 16 + r0;
            int gcg = n0 + wn + ni * 8 + c0;
            float v0 = acc[mi][ni][0], v1 = acc[mi][ni][1];
            float v2 = acc[mi][ni][2], v3 = acc[mi][ni][3];
            if (bias) {
                float2 bb = *(const float2*)&bias[gcg];
                v0 += bb.x; v1 += bb.y; v2 += bb.x; v3 += bb.y;
            }
            if (addm) {
                float2 a0 = *(const float2*)&addm[(size_t)gr * addld + gcg];
                float2 a1 = *(const float2*)&addm[(size_t)(gr + 8) * addld + gcg];
                v0 += a0.x; v1 += a0.y; v2 += a1.x; v3 += a1.y;
            }
            *(float2*)&C[(size_t)gr * ldc + gcg] = make_float2(v0, v1);
            *(float2*)&C[(size_t)(gr + 8) * ldc + gcg] = make_float2(v2, v3);
        }
}

// ---------------- batch-grouped persistent loop: 8 groups x 16 blocks ----------------
// smem layout (floats)
#define SWA   0          // [64m][256h]   Wm1 slice          16384
#define SWC   16384      // [64m][32o]    Wm2-head slice      2048
#define SX    18432      // [64m][8b]     mem slice            512
#define SV    18944      // [256h][8b]    v1 chunk            2048
#define SRED  20992      // [8w][32o][9]  Bv partial reduce   2304
#define STOT  23296

__global__ void __launch_bounds__(256, 1) loop_kernel(const float* __restrict__ Wm1,
                                                      const float* __restrict__ W12,
                                                      const float* __restrict__ Wm2,
                                                      float* __restrict__ out) {
    extern __shared__ float sm[];
    float* sWA = sm + SWA;
    float* sWC = sm + SWC;
    float* sX  = sm + SX;
    float* sV  = sm + SV;
    float* sRd = sm + SRED;

    const int tid = threadIdx.x;
    const int g   = blockIdx.x >> 4;            // group
    const int j   = blockIdx.x & 15;            // role within group
    const int ht  = j >> 2, mc = j & 3;         // P1 role: h-tile(256), m-chunk(64)
    const int ot  = j >> 2, kc = j & 3;         // P2 role: o-tile(32), k-chunk(256)
    const int B0  = g * GB;

    // --- one-time weight staging ---
    for (int i = tid; i < 64 * 256; i += 256) {
        int ml = i >> 8, hl = i & 255;
        sWA[ml * 256 + hl] = Wm1[(ht * 256 + hl) * 256 + mc * 64 + ml];
    }
    for (int i = tid; i < 64 * 32; i += 256) {
        int ml = i >> 5, oy = i & 31;
        sWC[ml * 32 + oy] = Wm2[(ht * 32 + oy) * 256 + mc * 64 + ml];
    }
    const int warp = tid >> 5, lane = tid & 31;
    float wreg[32];
    {
        int o = ot * 32 + lane;
#pragma unroll
        for (int kk = 0; kk < 32; kk++)
            wreg[kk] = W12[o * 1024 + kc * 256 + warp * 32 + kk];
    }
    __syncthreads();

    // thread mappings
    const int hy = tid >> 1, bq = tid & 1;          // P1 compute: 2h x 4b
    const int oy = tid & 31, bi = tid >> 5;         // Am / Bv-reduce: 1o x 1b
    const int bl2 = tid & 7, hq = tid >> 3;         // P2 assembly: 8h x 1b
    const bool logV = ((hq >> 3) == ot);            // P2: this block logs hl in [ot*64,ot*64+64)

    unsigned tgt = GBLK;
    unsigned* cnt = &g_cnt[g * 32];

    for (int t = 0; t < NT; t++) {
        const int par0 = t & 1, par1 = par0 ^ 1;
        // ===== P1: assemble mem slice =====
        if (t == 0) {
#pragma unroll
            for (int i = 0; i < 2; i++) {
                int v = tid * 2 + i, ml = v >> 3, bl = v & 7;
                sX[ml * 8 + bl] = g_mem0T[(mc * 64 + ml) * 64 + B0 + bl];
            }
        } else if (mc < 2) {
#pragma unroll
            for (int i = 0; i < 2; i++) {
                int v = tid * 2 + i, ml = v >> 3, bl = v & 7;
                sX[ml * 8 + bl] = __ldcg(&g_v1T[(mc * 64 + ml) * 64 + B0 + bl]);
            }
        } else {
#pragma unroll
            for (int i = 0; i < 2; i++) {
                int v = tid * 2 + i, ml = v >> 3, bl = v & 7;
                int o = mc * 64 + ml - 128;
                int b = B0 + bl;
                float s = g_pre2[(size_t)(b * NT + t - 1) * 512 + o];
#pragma unroll
                for (int q = 0; q < 4; q++) {
                    s += __ldcg(&g_Am[par1][(((g * 4 + q) * 128) + o) * 8 + bl]);
                    s += __ldcg(&g_Bv[(((g * 4 + q) * 128) + o) * 8 + bl]);
                }
                s = sigmoid_fast(s);
                sX[ml * 8 + bl] = s;
                if ((ml >> 4) == ht)   // straggler-balanced out write
                    __stcg(&out[(size_t)(b * NT + t - 1) * 512 + o], s);
            }
        }
        __syncthreads();
        // At3 mem-part logging, balanced: each ht block writes its 16-m quarter
        if (tid < 128) {
            int ml = ht * 16 + (tid >> 3), bl = tid & 7;
            float x = sX[ml * 8 + bl];
            __nv_bfloat16 h = __float2bfloat16(x);
            __nv_bfloat16 l = __float2bfloat16(x - __bfloat162float(h));
            int m = mc * 64 + ml;
            size_t base = (size_t)((B0 + bl) * NT + t) * 3840;
            g_At3[base + 1024 + m] = h;
            g_At3[base + 2304 + m] = h;
            g_At3[base + 3584 + m] = l;
        }
        // ===== P1 compute: Apart (256h x 8b over 64m) =====
        {
            float acc[2][4] = {};
#pragma unroll 16
            for (int m = 0; m < 64; m++) {
                float2 w = *(float2*)&sWA[m * 256 + hy * 2];
                float4 x = *(float4*)&sX[m * 8 + bq * 4];
                acc[0][0] += w.x * x.x; acc[0][1] += w.x * x.y; acc[0][2] += w.x * x.z; acc[0][3] += w.x * x.w;
                acc[1][0] += w.y * x.x; acc[1][1] += w.y * x.y; acc[1][2] += w.y * x.z; acc[1][3] += w.y * x.w;
            }
#pragma unroll
            for (int r = 0; r < 2; r++) {
                int hg = ht * 256 + hy * 2 + r;
                __stcg((float4*)&g_Apart[((g * 4 + mc) * 1024 + hg) * 8 + bq * 4],
                       make_float4(acc[r][0], acc[r][1], acc[r][2], acc[r][3]));
            }
        }
        // ===== P1 compute: Am (32o x 8b over 64m) =====
        {
            float a = 0.f;
#pragma unroll 16
            for (int m = 0; m < 64; m++) a += sWC[m * 32 + oy] * sX[m * 8 + bi];
            __stcg(&g_Am[par0][((g * 4 + mc) * 128 + ht * 32 + oy) * 8 + bi], a);
        }
        // barrier 1
        __syncthreads();
        if (tid == 0) {
            __threadfence();
            atomicAdd(cnt, 1u);
            while (*(volatile unsigned*)cnt < tgt) { }
        }
        __syncthreads();
        tgt += GBLK;

        // ===== P2: assemble v1 chunk (256h x 8b) + balanced At3 v1 logging =====
        {
            const int b = B0 + bl2;
            const size_t prow = (size_t)(b * NT + t) * 1024 + kc * 256;
            const size_t rowbase = (size_t)(b * NT + t) * 3840;
            const bool isTanh = (kc < 2);
#pragma unroll
            for (int i = 0; i < 8; i++) {
                int hl = hq * 8 + i;
                float s = g_pre1[prow + hl];
#pragma unroll
                for (int q = 0; q < 4; q++)
                    s += __ldcg(&g_Apart[((g * 4 + q) * 1024 + kc * 256 + hl) * 8 + bl2]);
                s = isTanh ? tanh_fast(s) : fmaxf(s, 0.f);
                sV[hl * 8 + bl2] = s;
                if (logV) {
                    __nv_bfloat16 h = __float2bfloat16(s);
                    __nv_bfloat16 l = __float2bfloat16(s - __bfloat162float(h));
                    int hgl = kc * 256 + hl;
                    g_At3[rowbase + hgl] = h;
                    g_At3[rowbase + 1280 + hgl] = h;
                    g_At3[rowbase + 2560 + hgl] = l;
                    if (kc == 0 && hl < 128) __stcg(&g_v1T[hl * 64 + b], s);
                }
            }
        }
        __syncthreads();
        // ===== P2 compute: Bv (32o x 8b over own 32k via register weights) =====
        {
            float a8[8] = {};
#pragma unroll
            for (int kk = 0; kk < 32; kk++) {
                int hl = warp * 32 + kk;
                float w = wreg[kk];
#pragma unroll
                for (int b = 0; b < 8; b++) a8[b] += w * sV[hl * 8 + b];
            }
#pragma unroll
            for (int b = 0; b < 8; b++) sRd[(warp * 32 + lane) * 9 + b] = a8[b];
        }
        __syncthreads();
        {
            float s = 0.f;
#pragma unroll
            for (int w = 0; w < 8; w++) s += sRd[(w * 32 + oy) * 9 + bi];
            __stcg(&g_Bv[((g * 4 + kc) * 128 + ot * 32 + oy) * 8 + bi], s);
        }
        // barrier 2
        __syncthreads();
        if (tid == 0) {
            __threadfence();
            atomicAdd(cnt, 1u);
            while (*(volatile unsigned*)cnt < tgt) { }
        }
        __syncthreads();
        tgt += GBLK;
    }

    // ===== epilogue: out head for t = NT-1 (balanced) =====
    if (mc >= 2) {
#pragma unroll
        for (int i = 0; i < 2; i++) {
            int v = tid * 2 + i, ml = v >> 3, bl = v & 7;
            if ((ml >> 4) != ht) continue;
            int o = mc * 64 + ml - 128;
            int b = B0 + bl;
            float s = g_pre2[(size_t)(b * NT + NT - 1) * 512 + o];
#pragma unroll
            for (int q = 0; q < 4; q++) {
                s += __ldcg(&g_Am[(NT - 1) & 1][(((g * 4 + q) * 128) + o) * 8 + bl]);
                s += __ldcg(&g_Bv[(((g * 4 + q) * 128) + o) * 8 + bl]);
            }
            s = sigmoid_fast(s);
            __stcg(&out[(size_t)(b * NT + NT - 1) * 512 + o], s);
        }
    }
}

// ---------------- launch ----------------
extern "C" void kernel_launch(void* const* d_in, const int* in_sizes, int n_in,
                              void* d_out, int out_size) {
    const float* X   = (const float*)d_in[0];
    const float* mem = (const float*)d_in[1];
    const float* W01 = (const float*)d_in[2];
    const float* b01 = (const float*)d_in[3];
    const float* W02 = (const float*)d_in[4];
    const float* b02 = (const float*)d_in[5];
    const float* W12 = (const float*)d_in[6];
    const float* b12 = (const float*)d_in[7];
    const float* Wm1 = (const float*)d_in[8];
    const float* bm1 = (const float*)d_in[9];
    const float* Wm2 = (const float*)d_in[10];
    const float* bm2 = (const float*)d_in[11];
    float* out = (float*)d_out;

    float *pre1, *pre2, *b1, *b2;
    __nv_bfloat16 *X3, *W013, *W023, *Wt3, *At3;
    cudaGetSymbolAddress((void**)&pre1, g_pre1);
    cudaGetSymbolAddress((void**)&pre2, g_pre2);
    cudaGetSymbolAddress((void**)&b1, g_bias1);
    cudaGetSymbolAddress((void**)&b2, g_bias2);
    cudaGetSymbolAddress((void**)&X3, g_X3);
    cudaGetSymbolAddress((void**)&W013, g_W013);
    cudaGetSymbolAddress((void**)&W023, g_W023);
    cudaGetSymbolAddress((void**)&Wt3, g_Wt3);
    cudaGetSymbolAddress((void**)&At3, g_At3);

    const int HG_SMEM = STG * 128 * 40 * 2 * (int)sizeof(__nv_bfloat16);
    cudaFuncSetAttribute(hgemm_kernel, cudaFuncAttributeMaxDynamicSharedMemorySize, HG_SMEM);
    cudaFuncSetAttribute(loop_kernel, cudaFuncAttributeMaxDynamicSharedMemorySize,
                         STOT * (int)sizeof(float));

    prep_kernel<<<32, 256>>>(b01, bm1, b02, b12, bm2, mem);
    split3_kernel<<<2048, 256>>>(X, X3, 512, NROWS * 512, 1);
    split3_kernel<<<512, 256>>>(W01, W013, 512, 1024 * 512, 0);
    split3_kernel<<<256, 256>>>(W02, W023, 512, 512 * 512, 0);
    splitWtail_kernel<<<512, 256>>>(W12, Wm2);
    hgemm_kernel<<<dim3(8, NROWS / 128), 256, HG_SMEM>>>(X3, W013, 1536, pre1, 1024, b1, nullptr, 0);
    hgemm_kernel<<<dim3(4, NROWS / 128), 256, HG_SMEM>>>(X3, W023, 1536, pre2, 512, b2, nullptr, 0);
    loop_kernel<<<NGRP * GBLK, 256, STOT * sizeof(float)>>>(Wm1, W12, Wm2, out);
    hgemm_kernel<<<dim3(3, NROWS / 128), 256, HG_SMEM>>>(At3, Wt3, 3840, out + 128, 512,
                                                         nullptr, pre2 + 128, 512);
}

// round 12
// speedup vs baseline: 1.5168x; 1.0809x over previous
#include <cuda_runtime.h>
#include <cuda_bf16.h>
#include <cstdint>
#include <math.h>

#define NBATCH 64
#define NT     512
#define NROWS  (NBATCH * NT)
#define NGRP   8          // batch groups
#define GB     8          // batch per group
#define GBLK   16         // blocks per group

// ---------------- device scratch ----------------
__device__ float g_pre1[NROWS * 1024];
__device__ float g_pre2[NROWS * 512];
__device__ float g_v1Tn[2 * NGRP * 128 * 8];       // [par][g][h<128][bl]
__device__ float g_Bv[2 * NGRP * 16 * 128 * 8];    // [par][g][j][o][bl]
__device__ float g_mem0T[256 * 64];                // initial memory [m][b]
__device__ float g_bias1[1024];
__device__ float g_bias2[512];
__device__ unsigned g_cnt[NGRP * 32];              // per-group barrier counters, padded
// bf16 split operands (K-concat trick)
__device__ __nv_bfloat16 g_X3[NROWS * 1536];       // [Ah|Ah|Al]
__device__ __nv_bfloat16 g_W013[1024 * 1536];      // [Wh|Wl|Wh]
__device__ __nv_bfloat16 g_W023[512 * 1536];
__device__ __nv_bfloat16 g_Wt3[384 * 3840];
__device__ __nv_bfloat16 g_At3[NROWS * 3840];      // filled by the loop

__device__ __forceinline__ float sigmoid_fast(float x) {
    return 1.f / (1.f + __expf(-x));
}
__device__ __forceinline__ float tanh_fast(float x) {
    float e = __expf(2.f * x);
    return 1.f - 2.f / (e + 1.f);
}

// ---------------- prep ----------------
__global__ void prep_kernel(const float* __restrict__ b01, const float* __restrict__ bm1,
                            const float* __restrict__ b02, const float* __restrict__ b12,
                            const float* __restrict__ bm2, const float* __restrict__ memory) {
    int i = blockIdx.x * blockDim.x + threadIdx.x;
    int n = gridDim.x * blockDim.x;
    if (i < NGRP) g_cnt[i * 32] = 0u;
    for (int j = i; j < 1024; j += n) g_bias1[j] = b01[j] + bm1[j];
    for (int j = i; j < 512; j += n) g_bias2[j] = b02[j] + b12[j] + bm2[j];
    for (int j = i; j < 256 * 64; j += n) {
        int m = j >> 6, b = j & 63;
        g_mem0T[j] = memory[b * 256 + m];
    }
}

// split fp32 -> bf16 hi/lo, K-concat. aMode: [h|h|l]  else (W): [h|l|h]
__global__ void split3_kernel(const float* __restrict__ src, __nv_bfloat16* __restrict__ dst,
                              int K, int total, int aMode) {
    for (int i = blockIdx.x * blockDim.x + threadIdx.x; i < total; i += gridDim.x * blockDim.x) {
        int r = i / K, k = i % K;
        float x = src[i];
        __nv_bfloat16 h = __float2bfloat16(x);
        __nv_bfloat16 l = __float2bfloat16(x - __bfloat162float(h));
        __nv_bfloat16* d = dst + (size_t)r * 3 * K + k;
        d[0] = h;
        d[K] = aMode ? h : l;
        d[2 * K] = aMode ? l : h;
    }
}

__global__ void splitWtail_kernel(const float* __restrict__ W12, const float* __restrict__ Wm2) {
    for (int i = blockIdx.x * blockDim.x + threadIdx.x; i < 384 * 1280; i += gridDim.x * blockDim.x) {
        int o = i / 1280, k = i % 1280;
        float x = (k < 1024) ? W12[(o + 128) * 1024 + k] : Wm2[(o + 128) * 256 + (k - 1024)];
        __nv_bfloat16 h = __float2bfloat16(x);
        __nv_bfloat16 l = __float2bfloat16(x - __bfloat162float(h));
        __nv_bfloat16* d = g_Wt3 + (size_t)o * 3840 + k;
        d[0] = h; d[1280] = l; d[2560] = h;
    }
}

// ---------------- bf16 tensor-core GEMM with 3-stage cp.async pipeline ----------------
#define STG 3

__device__ __forceinline__ void cp16(uint32_t s, const void* g) {
    asm volatile("cp.async.cg.shared.global [%0], [%1], 16;" :: "r"(s), "l"(g));
}

__global__ void __launch_bounds__(256) hgemm_kernel(const __nv_bfloat16* __restrict__ A,
                                                    const __nv_bfloat16* __restrict__ W, int K,
                                                    float* __restrict__ C, int ldc,
                                                    const float* __restrict__ bias,
                                                    const float* __restrict__ addm, int addld) {
    extern __shared__ __nv_bfloat16 hsm[];
    __nv_bfloat16 (*sA)[128][40] = (__nv_bfloat16(*)[128][40])hsm;
    __nv_bfloat16 (*sW)[128][40] = (__nv_bfloat16(*)[128][40])(hsm + STG * 128 * 40);
    const int tid = threadIdx.x;
    const int n0 = blockIdx.x * 128, m0 = blockIdx.y * 128;
    const int warp = tid >> 5, lane = tid & 31;
    const int wm = (warp >> 1) * 32, wn = (warp & 1) * 64;
    const int lr = tid >> 1, lc = (tid & 1) * 16;
    float acc[2][8][4] = {};
    const __nv_bfloat16* Ag = A + (size_t)(m0 + lr) * K + lc;
    const __nv_bfloat16* Wg = W + (size_t)(n0 + lr) * K + lc;
    uint32_t aAddr[STG], wAddr[STG];
#pragma unroll
    for (int s = 0; s < STG; s++) {
        aAddr[s] = (uint32_t)__cvta_generic_to_shared(&sA[s][lr][lc]);
        wAddr[s] = (uint32_t)__cvta_generic_to_shared(&sW[s][lr][lc]);
    }
    const int nsteps = K / 32;
#define HG_ISSUE(s) do { \
        int _st = (s) % STG; \
        const __nv_bfloat16* _ap = Ag + (size_t)(s) * 32; \
        const __nv_bfloat16* _wp = Wg + (size_t)(s) * 32; \
        cp16(aAddr[_st], _ap); cp16(aAddr[_st] + 16, _ap + 8); \
        cp16(wAddr[_st], _wp); cp16(wAddr[_st] + 16, _wp + 8); \
        asm volatile("cp.async.commit_group;"); \
    } while (0)
    HG_ISSUE(0);
    HG_ISSUE(1);
    asm volatile("cp.async.wait_group 1;");
    __syncthreads();
    for (int s = 0; s < nsteps; s++) {
        if (s + 2 < nsteps) HG_ISSUE(s + 2);
        const int cur = s % STG;
#pragma unroll
        for (int kf = 0; kf < 2; kf++) {
            const int acol = kf * 16 + (lane & 3) * 2;
            const int arow = wm + (lane >> 2);
            uint32_t af[2][4], bfr[8][2];
#pragma unroll
            for (int mi = 0; mi < 2; mi++) {
                af[mi][0] = *(uint32_t*)&sA[cur][arow + mi * 16][acol];
                af[mi][1] = *(uint32_t*)&sA[cur][arow + mi * 16 + 8][acol];
                af[mi][2] = *(uint32_t*)&sA[cur][arow + mi * 16][acol + 8];
                af[mi][3] = *(uint32_t*)&sA[cur][arow + mi * 16 + 8][acol + 8];
            }
#pragma unroll
            for (int ni = 0; ni < 8; ni++) {
                bfr[ni][0] = *(uint32_t*)&sW[cur][wn + ni * 8 + (lane >> 2)][acol];
                bfr[ni][1] = *(uint32_t*)&sW[cur][wn + ni * 8 + (lane >> 2)][acol + 8];
            }
#pragma unroll
            for (int mi = 0; mi < 2; mi++)
#pragma unroll
                for (int ni = 0; ni < 8; ni++)
                    asm volatile(
                        "mma.sync.aligned.m16n8k16.row.col.f32.bf16.bf16.f32 "
                        "{%0,%1,%2,%3}, {%4,%5,%6,%7}, {%8,%9}, {%0,%1,%2,%3};"
                        : "+f"(acc[mi][ni][0]), "+f"(acc[mi][ni][1]),
                          "+f"(acc[mi][ni][2]), "+f"(acc[mi][ni][3])
                        : "r"(af[mi][0]), "r"(af[mi][1]), "r"(af[mi][2]), "r"(af[mi][3]),
                          "r"(bfr[ni][0]), "r"(bfr[ni][1]));
        }
        asm volatile("cp.async.wait_group 1;");
        __syncthreads();
    }
    const int r0 = lane >> 2, c0 = (lane & 3) * 2;
#pragma unroll
    for (int mi = 0; mi < 2; mi++)
#pragma unroll
        for (int ni = 0; ni < 8; ni++) {
            int gr = m0 + wm + mi * 16 + r0;
            int gcg = n0 + wn + ni * 8 + c0;
            float v0 = acc[mi][ni][0], v1 = acc[mi][ni][1];
            float v2 = acc[mi][ni][2], v3 = acc[mi][ni][3];
            if (bias) {
                float2 bb = *(const float2*)&bias[gcg];
                v0 += bb.x; v1 += bb.y; v2 += bb.x; v3 += bb.y;
            }
            if (addm) {
                float2 a0 = *(const float2*)&addm[(size_t)gr * addld + gcg];
                float2 a1 = *(const float2*)&addm[(size_t)(gr + 8) * addld + gcg];
                v0 += a0.x; v1 += a0.y; v2 += a1.x; v3 += a1.y;
            }
            *(float2*)&C[(size_t)gr * ldc + gcg] = make_float2(v0, v1);
            *(float2*)&C[(size_t)(gr + 8) * ldc + gcg] = make_float2(v2, v3);
        }
}

// ---------------- one-barrier batch-grouped persistent loop ----------------
// Block j of group g: owns v1 rows [64j, 64j+64), W12 cols for that slice,
// Wm2 cols [16j,16j+16), out cols [8j,8j+8).
// smem layout (floats):
#define SWM1  0          // [256m][64h]   Wm1 slice    16384
#define SWB   16384      // [80k][128o]   W12|Wm2      10240
#define SMEM  26624      // [256m][8b]                  2048
#define SV    28672      // [64h][8b]                    512
#define SRED  29184      // [8w][64h][8b]                4096
#define STOT  33280

__global__ void __launch_bounds__(256, 1) loop_kernel(const float* __restrict__ Wm1,
                                                      const float* __restrict__ W12,
                                                      const float* __restrict__ Wm2,
                                                      float* __restrict__ out) {
    extern __shared__ float sm[];
    float* sWm1 = sm + SWM1;
    float* sWB  = sm + SWB;
    float* sMem = sm + SMEM;
    float* sV   = sm + SV;
    float* sRd  = sm + SRED;

    const int tid = threadIdx.x;
    const int g   = blockIdx.x >> 4;
    const int j   = blockIdx.x & 15;
    const int B0  = g * GB;
    const int warp = tid >> 5, lane = tid & 31;

    // one-time weight staging
    for (int i = tid; i < 64 * 256; i += 256) {        // sWm1[m][h]
        int m = i >> 6, h = i & 63;
        sWm1[m * 64 + h] = Wm1[(j * 64 + h) * 256 + m];
    }
    for (int i = tid; i < 80 * 128; i += 256) {        // sWB[k][o]
        int k = i >> 7, o = i & 127;
        sWB[i] = (k < 64) ? W12[o * 1024 + j * 64 + k]
                          : Wm2[o * 256 + j * 16 + (k - 64)];
    }
    __syncthreads();

    unsigned tgt = GBLK;
    unsigned* cnt = &g_cnt[g * 32];

    for (int t = 0; t < NT; t++) {
        const int par0 = t & 1, par1 = par0 ^ 1;
        // ===== 1) assemble mem[256m][8b] (redundant per block) =====
        if (t == 0) {
#pragma unroll
            for (int i = 0; i < 8; i++) {
                int e = tid + 256 * i;
                int m = e >> 3, b = e & 7;
                sMem[e] = g_mem0T[m * 64 + B0 + b];
            }
        } else {
#pragma unroll
            for (int i = 0; i < 8; i++) {
                int e = tid + 256 * i;
                int m = e >> 3, b = e & 7;
                float s;
                if (m < 128) {
                    s = __ldcg(&g_v1Tn[((par1 * NGRP + g) * 128 + m) * 8 + b]);
                } else {
                    int o = m - 128;
                    s = __ldcg(&g_pre2[(size_t)((B0 + b) * NT + t - 1) * 512 + o]);
#pragma unroll
                    for (int q = 0; q < 16; q++)
                        s += __ldcg(&g_Bv[((par1 * NGRP + g) * 16 + q) * 1024 + o * 8 + b]);
                    s = sigmoid_fast(s);
                    if ((o >> 3) == j)
                        __stcg(&out[(size_t)((B0 + b) * NT + t - 1) * 512 + o], s);
                }
                sMem[e] = s;
            }
        }
        __syncthreads();
        // At3 mem-part logging (own 16-m slice)
        if (tid < 128) {
            int ml = j * 16 + (tid >> 3), b = tid & 7;
            float x = sMem[ml * 8 + b];
            __nv_bfloat16 h = __float2bfloat16(x);
            __nv_bfloat16 l = __float2bfloat16(x - __bfloat162float(h));
            size_t base = (size_t)((B0 + b) * NT + t) * 3840;
            g_At3[base + 1024 + ml] = h;
            g_At3[base + 2304 + ml] = h;
            g_At3[base + 3584 + ml] = l;
        }
        // ===== 2) GEMM1: v1 slice [64h x 8b] over K=256, warp K-split =====
        {
            float acc[16] = {};
            const int mBase = warp * 32;
#pragma unroll 8
            for (int mm = 0; mm < 32; mm++) {
                int m = mBase + mm;
                float2 wv = *(float2*)&sWm1[m * 64 + lane * 2];
                float4 x0 = *(float4*)&sMem[m * 8];
                float4 x1 = *(float4*)&sMem[m * 8 + 4];
                acc[0] += wv.x * x0.x; acc[1] += wv.x * x0.y; acc[2] += wv.x * x0.z; acc[3] += wv.x * x0.w;
                acc[4] += wv.x * x1.x; acc[5] += wv.x * x1.y; acc[6] += wv.x * x1.z; acc[7] += wv.x * x1.w;
                acc[8]  += wv.y * x0.x; acc[9]  += wv.y * x0.y; acc[10] += wv.y * x0.z; acc[11] += wv.y * x0.w;
                acc[12] += wv.y * x1.x; acc[13] += wv.y * x1.y; acc[14] += wv.y * x1.z; acc[15] += wv.y * x1.w;
            }
#pragma unroll
            for (int hh = 0; hh < 2; hh++) {
                int base = warp * 512 + (lane * 2 + hh) * 8;
                *(float4*)&sRd[base]     = make_float4(acc[hh * 8 + 0], acc[hh * 8 + 1], acc[hh * 8 + 2], acc[hh * 8 + 3]);
                *(float4*)&sRd[base + 4] = make_float4(acc[hh * 8 + 4], acc[hh * 8 + 5], acc[hh * 8 + 6], acc[hh * 8 + 7]);
            }
        }
        __syncthreads();
        // ===== 3) reduce + activation + v1T/At3 writes =====
#pragma unroll
        for (int i = 0; i < 2; i++) {
            int e = tid + 256 * i;
            int h = e >> 3, b = e & 7;
            float s = sRd[e] + sRd[512 + e] + sRd[1024 + e] + sRd[1536 + e]
                    + sRd[2048 + e] + sRd[2560 + e] + sRd[3072 + e] + sRd[3584 + e];
            int hg = j * 64 + h;
            size_t row = (size_t)(B0 + b) * NT + t;
            s += __ldcg(&g_pre1[row * 1024 + hg]);
            s = (hg < 512) ? tanh_fast(s) : fmaxf(s, 0.f);
            sV[e] = s;
            if (hg < 128)
                __stcg(&g_v1Tn[((par0 * NGRP + g) * 128 + hg) * 8 + b], s);
            __nv_bfloat16 hh = __float2bfloat16(s);
            __nv_bfloat16 ll = __float2bfloat16(s - __bfloat162float(hh));
            size_t base = row * 3840;
            g_At3[base + hg] = hh;
            g_At3[base + 1280 + hg] = hh;
            g_At3[base + 2560 + hg] = ll;
        }
        __syncthreads();
        // ===== 4) GEMM2: Bv_j[128o x 8b] over own 64 v1-k + 16 mem-m =====
        {
            const int oq = tid >> 3, b = tid & 7;
            float a0 = 0.f, a1 = 0.f, a2 = 0.f, a3 = 0.f;
#pragma unroll 8
            for (int k = 0; k < 64; k++) {
                float4 wv = *(float4*)&sWB[k * 128 + oq * 4];
                float x = sV[k * 8 + b];
                a0 += wv.x * x; a1 += wv.y * x; a2 += wv.z * x; a3 += wv.w * x;
            }
#pragma unroll
            for (int k = 0; k < 16; k++) {
                float4 wv = *(float4*)&sWB[(64 + k) * 128 + oq * 4];
                float x = sMem[(j * 16 + k) * 8 + b];
                a0 += wv.x * x; a1 += wv.y * x; a2 += wv.z * x; a3 += wv.w * x;
            }
            size_t ob = (size_t)((par0 * NGRP + g) * 16 + j) * 1024 + (oq * 4) * 8 + b;
            __stcg(&g_Bv[ob], a0);
            __stcg(&g_Bv[ob + 8], a1);
            __stcg(&g_Bv[ob + 16], a2);
            __stcg(&g_Bv[ob + 24], a3);
        }
        // ===== 5) group barrier =====
        __syncthreads();
        if (tid == 0) {
            __threadfence();
            atomicAdd(cnt, 1u);
            while (*(volatile unsigned*)cnt < tgt) { }
        }
        __syncthreads();
        tgt += GBLK;
    }

    // ===== epilogue: out head for t = NT-1 =====
    {
        const int parL = (NT - 1) & 1;
        if (tid < 64) {
            int o = j * 8 + (tid >> 3), b = tid & 7;
            float s = __ldcg(&g_pre2[(size_t)((B0 + b) * NT + NT - 1) * 512 + o]);
#pragma unroll
            for (int q = 0; q < 16; q++)
                s += __ldcg(&g_Bv[((parL * NGRP + g) * 16 + q) * 1024 + o * 8 + b]);
            s = sigmoid_fast(s);
            __stcg(&out[(size_t)((B0 + b) * NT + NT - 1) * 512 + o], s);
        }
    }
}

// ---------------- launch ----------------
extern "C" void kernel_launch(void* const* d_in, const int* in_sizes, int n_in,
                              void* d_out, int out_size) {
    const float* X   = (const float*)d_in[0];
    const float* mem = (const float*)d_in[1];
    const float* W01 = (const float*)d_in[2];
    const float* b01 = (const float*)d_in[3];
    const float* W02 = (const float*)d_in[4];
    const float* b02 = (const float*)d_in[5];
    const float* W12 = (const float*)d_in[6];
    const float* b12 = (const float*)d_in[7];
    const float* Wm1 = (const float*)d_in[8];
    const float* bm1 = (const float*)d_in[9];
    const float* Wm2 = (const float*)d_in[10];
    const float* bm2 = (const float*)d_in[11];
    float* out = (float*)d_out;

    float *pre1, *pre2, *b1, *b2;
    __nv_bfloat16 *X3, *W013, *W023, *Wt3, *At3;
    cudaGetSymbolAddress((void**)&pre1, g_pre1);
    cudaGetSymbolAddress((void**)&pre2, g_pre2);
    cudaGetSymbolAddress((void**)&b1, g_bias1);
    cudaGetSymbolAddress((void**)&b2, g_bias2);
    cudaGetSymbolAddress((void**)&X3, g_X3);
    cudaGetSymbolAddress((void**)&W013, g_W013);
    cudaGetSymbolAddress((void**)&W023, g_W023);
    cudaGetSymbolAddress((void**)&Wt3, g_Wt3);
    cudaGetSymbolAddress((void**)&At3, g_At3);

    const int HG_SMEM = STG * 128 * 40 * 2 * (int)sizeof(__nv_bfloat16);
    cudaFuncSetAttribute(hgemm_kernel, cudaFuncAttributeMaxDynamicSharedMemorySize, HG_SMEM);
    cudaFuncSetAttribute(loop_kernel, cudaFuncAttributeMaxDynamicSharedMemorySize,
                         STOT * (int)sizeof(float));

    prep_kernel<<<32, 256>>>(b01, bm1, b02, b12, bm2, mem);
    split3_kernel<<<2048, 256>>>(X, X3, 512, NROWS * 512, 1);
    split3_kernel<<<512, 256>>>(W01, W013, 512, 1024 * 512, 0);
    split3_kernel<<<256, 256>>>(W02, W023, 512, 512 * 512, 0);
    splitWtail_kernel<<<512, 256>>>(W12, Wm2);
    hgemm_kernel<<<dim3(8, NROWS / 128), 256, HG_SMEM>>>(X3, W013, 1536, pre1, 1024, b1, nullptr, 0);
    hgemm_kernel<<<dim3(4, NROWS / 128), 256, HG_SMEM>>>(X3, W023, 1536, pre2, 512, b2, nullptr, 0);
    loop_kernel<<<NGRP * GBLK, 256, STOT * sizeof(float)>>>(Wm1, W12, Wm2, out);
    hgemm_kernel<<<dim3(3, NROWS / 128), 256, HG_SMEM>>>(At3, Wt3, 3840, out + 128, 512,
                                                         nullptr, pre2 + 128, 512);
}

// round 13
// speedup vs baseline: 1.5650x; 1.0318x over previous
#include <cuda_runtime.h>
#include <cuda_bf16.h>
#include <cstdint>
#include <math.h>

#define NBATCH 64
#define NT     512
#define NROWS  (NBATCH * NT)
#define NGRP   8          // batch groups
#define GB     8          // batch per group
#define GBLK   16         // blocks per group

// ---------------- device scratch ----------------
__device__ float g_pre1[NROWS * 1024];
__device__ float g_pre2[NROWS * 512];
__device__ float g_v1Tn[2 * NGRP * 8 * 128];       // [par][g][b][h<128]  (b-major)
__device__ float g_Bv[2 * NGRP * 16 * 8 * 128];    // [par][g][j][b][o]   (b-major)
__device__ float g_mem0T[256 * 64];                // initial memory [m][b]
__device__ float g_bias1[1024];
__device__ float g_bias2[512];
__device__ unsigned g_cnt[NGRP * 32];              // per-group barrier counters, padded
// bf16 split operands (K-concat, deduped hi)
__device__ __nv_bfloat16 g_X2[NROWS * 1024];       // [Xh|Xl]
__device__ __nv_bfloat16 g_W013[1024 * 1536];      // [Wh|Wl|Wh]
__device__ __nv_bfloat16 g_W023[512 * 1536];
__device__ __nv_bfloat16 g_Wt3[384 * 3840];        // [Wh|Wl|Wh] over K=1280
__device__ __nv_bfloat16 g_At2[NROWS * 2560];      // [v1h|memh | v1l|meml], filled by loop

__device__ __forceinline__ float sigmoid_fast(float x) {
    return 1.f / (1.f + __expf(-x));
}
__device__ __forceinline__ float tanh_fast(float x) {
    float e = __expf(2.f * x);
    return 1.f - 2.f / (e + 1.f);
}

// ---------------- fused prep: biases, mem transpose, all bf16 splits ----------------
__global__ void prep_all(const float* __restrict__ b01, const float* __restrict__ bm1,
                         const float* __restrict__ b02, const float* __restrict__ b12,
                         const float* __restrict__ bm2, const float* __restrict__ memory,
                         const float* __restrict__ X, const float* __restrict__ W01,
                         const float* __restrict__ W02, const float* __restrict__ W12,
                         const float* __restrict__ Wm2) {
    const int gid = blockIdx.x * blockDim.x + threadIdx.x;
    const int n = gridDim.x * blockDim.x;
    if (gid < NGRP) g_cnt[gid * 32] = 0u;
    for (int i = gid; i < 1024; i += n) g_bias1[i] = b01[i] + bm1[i];
    for (int i = gid; i < 512; i += n) g_bias2[i] = b02[i] + b12[i] + bm2[i];
    for (int i = gid; i < 256 * 64; i += n) {
        int m = i >> 6, b = i & 63;
        g_mem0T[i] = memory[b * 256 + m];
    }
    // X2: [h|l], row stride 1024
    for (int i = gid; i < NROWS * 512; i += n) {
        int r = i >> 9, k = i & 511;
        float x = X[i];
        __nv_bfloat16 h = __float2bfloat16(x);
        __nv_bfloat16 l = __float2bfloat16(x - __bfloat162float(h));
        __nv_bfloat16* d = g_X2 + (size_t)r * 1024 + k;
        d[0] = h; d[512] = l;
    }
    // W013: [h|l|h], row stride 1536
    for (int i = gid; i < 1024 * 512; i += n) {
        int r = i >> 9, k = i & 511;
        float x = W01[i];
        __nv_bfloat16 h = __float2bfloat16(x);
        __nv_bfloat16 l = __float2bfloat16(x - __bfloat162float(h));
        __nv_bfloat16* d = g_W013 + (size_t)r * 1536 + k;
        d[0] = h; d[512] = l; d[1024] = h;
    }
    for (int i = gid; i < 512 * 512; i += n) {
        int r = i >> 9, k = i & 511;
        float x = W02[i];
        __nv_bfloat16 h = __float2bfloat16(x);
        __nv_bfloat16 l = __float2bfloat16(x - __bfloat162float(h));
        __nv_bfloat16* d = g_W023 + (size_t)r * 1536 + k;
        d[0] = h; d[512] = l; d[1024] = h;
    }
    // Wt3: rows o=0..383 map to W12[o+128] (k<1024) / Wm2[o+128]; [h|l|h] over 1280
    for (int i = gid; i < 384 * 1280; i += n) {
        int o = i / 1280, k = i % 1280;
        float x = (k < 1024) ? W12[(o + 128) * 1024 + k] : Wm2[(o + 128) * 256 + (k - 1024)];
        __nv_bfloat16 h = __float2bfloat16(x);
        __nv_bfloat16 l = __float2bfloat16(x - __bfloat162float(h));
        __nv_bfloat16* d = g_Wt3 + (size_t)o * 3840 + k;
        d[0] = h; d[1280] = l; d[2560] = h;
    }
}

// ---------------- bf16 tensor-core GEMM, 3-stage cp.async, wrap-dedup A ----------------
#define STG 3

__device__ __forceinline__ void cp16(uint32_t s, const void* g) {
    asm volatile("cp.async.cg.shared.global [%0], [%1], 16;" :: "r"(s), "l"(g));
}

__global__ void __launch_bounds__(256) hgemm_kernel(const __nv_bfloat16* __restrict__ A,
                                                    int lda, int aHalf,
                                                    const __nv_bfloat16* __restrict__ W, int K,
                                                    float* __restrict__ C, int ldc,
                                                    const float* __restrict__ bias,
                                                    const float* __restrict__ addm, int addld) {
    extern __shared__ __nv_bfloat16 hsm[];
    __nv_bfloat16 (*sA)[128][40] = (__nv_bfloat16(*)[128][40])hsm;
    __nv_bfloat16 (*sW)[128][40] = (__nv_bfloat16(*)[128][40])(hsm + STG * 128 * 40);
    const int tid = threadIdx.x;
    const int n0 = blockIdx.x * 128, m0 = blockIdx.y * 128;
    const int warp = tid >> 5, lane = tid & 31;
    const int wm = (warp >> 1) * 32, wn = (warp & 1) * 64;
    const int lr = tid >> 1, lc = (tid & 1) * 16;
    float acc[2][8][4] = {};
    const __nv_bfloat16* Ag = A + (size_t)(m0 + lr) * lda + lc;
    const __nv_bfloat16* Wg = W + (size_t)(n0 + lr) * K + lc;
    uint32_t aAddr[STG], wAddr[STG];
#pragma unroll
    for (int s = 0; s < STG; s++) {
        aAddr[s] = (uint32_t)__cvta_generic_to_shared(&sA[s][lr][lc]);
        wAddr[s] = (uint32_t)__cvta_generic_to_shared(&sW[s][lr][lc]);
    }
    const int nsteps = K / 32;
#define HG_ISSUE(s) do { \
        int _st = (s) % STG; \
        int _sa = (aHalf && (s) >= aHalf) ? (s) - aHalf : (s); \
        const __nv_bfloat16* _ap = Ag + (size_t)_sa * 32; \
        const __nv_bfloat16* _wp = Wg + (size_t)(s) * 32; \
        cp16(aAddr[_st], _ap); cp16(aAddr[_st] + 16, _ap + 8); \
        cp16(wAddr[_st], _wp); cp16(wAddr[_st] + 16, _wp + 8); \
        asm volatile("cp.async.commit_group;"); \
    } while (0)
    HG_ISSUE(0);
    HG_ISSUE(1);
    asm volatile("cp.async.wait_group 1;");
    __syncthreads();
    for (int s = 0; s < nsteps; s++) {
        if (s + 2 < nsteps) HG_ISSUE(s + 2);
        const int cur = s % STG;
#pragma unroll
        for (int kf = 0; kf < 2; kf++) {
            const int acol = kf * 16 + (lane & 3) * 2;
            const int arow = wm + (lane >> 2);
            uint32_t af[2][4], bfr[8][2];
#pragma unroll
            for (int mi = 0; mi < 2; mi++) {
                af[mi][0] = *(uint32_t*)&sA[cur][arow + mi * 16][acol];
                af[mi][1] = *(uint32_t*)&sA[cur][arow + mi * 16 + 8][acol];
                af[mi][2] = *(uint32_t*)&sA[cur][arow + mi * 16][acol + 8];
                af[mi][3] = *(uint32_t*)&sA[cur][arow + mi * 16 + 8][acol + 8];
            }
#pragma unroll
            for (int ni = 0; ni < 8; ni++) {
                bfr[ni][0] = *(uint32_t*)&sW[cur][wn + ni * 8 + (lane >> 2)][acol];
                bfr[ni][1] = *(uint32_t*)&sW[cur][wn + ni * 8 + (lane >> 2)][acol + 8];
            }
#pragma unroll
            for (int mi = 0; mi < 2; mi++)
#pragma unroll
                for (int ni = 0; ni < 8; ni++)
                    asm volatile(
                        "mma.sync.aligned.m16n8k16.row.col.f32.bf16.bf16.f32 "
                        "{%0,%1,%2,%3}, {%4,%5,%6,%7}, {%8,%9}, {%0,%1,%2,%3};"
                        : "+f"(acc[mi][ni][0]), "+f"(acc[mi][ni][1]),
                          "+f"(acc[mi][ni][2]), "+f"(acc[mi][ni][3])
                        : "r"(af[mi][0]), "r"(af[mi][1]), "r"(af[mi][2]), "r"(af[mi][3]),
                          "r"(bfr[ni][0]), "r"(bfr[ni][1]));
        }
        asm volatile("cp.async.wait_group 1;");
        __syncthreads();
    }
    const int r0 = lane >> 2, c0 = (lane & 3) * 2;
#pragma unroll
    for (int mi = 0; mi < 2; mi++)
#pragma unroll
        for (int ni = 0; ni < 8; ni++) {
            int gr = m0 + wm + mi * 16 + r0;
            int gcg = n0 + wn + ni * 8 + c0;
            float v0 = acc[mi][ni][0], v1 = acc[mi][ni][1];
            float v2 = acc[mi][ni][2], v3 = acc[mi][ni][3];
            if (bias) {
                float2 bb = *(const float2*)&bias[gcg];
                v0 += bb.x; v1 += bb.y; v2 += bb.x; v3 += bb.y;
            }
            if (addm) {
                float2 a0 = *(const float2*)&addm[(size_t)gr * addld + gcg];
                float2 a1 = *(const float2*)&addm[(size_t)(gr + 8) * addld + gcg];
                v0 += a0.x; v1 += a0.y; v2 += a1.x; v3 += a1.y;
            }
            *(float2*)&C[(size_t)gr * ldc + gcg] = make_float2(v0, v1);
            *(float2*)&C[(size_t)(gr + 8) * ldc + gcg] = make_float2(v2, v3);
        }
}

// ---------------- one-barrier batch-grouped persistent loop (coalesced I/O) ----------
// smem layout (floats):
#define SWM1  0          // [256m][64h]   Wm1 slice    16384
#define SWB   16384      // [80k][128o]   W12|Wm2      10240
#define SMEM  26624      // [256m][8b]                  2048
#define SV    28672      // [64h][8b]                    512
#define SRED  29184      // [8w][64h][8b]                4096
#define STOT  33280

__global__ void __launch_bounds__(256, 1) loop_kernel(const float* __restrict__ Wm1,
                                                      const float* __restrict__ W12,
                                                      const float* __restrict__ Wm2,
                                                      float* __restrict__ out) {
    extern __shared__ float sm[];
    float* sWm1 = sm + SWM1;
    float* sWB  = sm + SWB;
    float* sMem = sm + SMEM;
    float* sV   = sm + SV;
    float* sRd  = sm + SRED;

    const int tid = threadIdx.x;
    const int g   = blockIdx.x >> 4;
    const int j   = blockIdx.x & 15;
    const int B0  = g * GB;
    const int warp = tid >> 5, lane = tid & 31;

    // one-time weight staging
    for (int i = tid; i < 64 * 256; i += 256) {        // sWm1[m][h]
        int m = i >> 6, h = i & 63;
        sWm1[m * 64 + h] = Wm1[(j * 64 + h) * 256 + m];
    }
    for (int i = tid; i < 80 * 128; i += 256) {        // sWB[k][o]
        int k = i >> 7, o = i & 127;
        sWB[i] = (k < 64) ? W12[o * 1024 + j * 64 + k]
                          : Wm2[o * 256 + j * 16 + (k - 64)];
    }
    __syncthreads();

    unsigned tgt = GBLK;
    unsigned* cnt = &g_cnt[g * 32];

    for (int t = 0; t < NT; t++) {
        const int par0 = t & 1, par1 = par0 ^ 1;
        // ===== 1) assemble mem[256m][8b] (coalesced global reads) =====
        if (t == 0) {
#pragma unroll
            for (int i = 0; i < 8; i++) {
                int e = tid + 256 * i;
                int m = e >> 3, b = e & 7;
                sMem[e] = g_mem0T[m * 64 + B0 + b];
            }
        } else {
            // part A: v1 head (h fastest)
#pragma unroll
            for (int i = 0; i < 4; i++) {
                int e = tid + 256 * i;
                int h = e & 127, b = e >> 7;
                sMem[h * 8 + b] = __ldcg(&g_v1Tn[((par1 * NGRP + g) * 8 + b) * 128 + h]);
            }
            // part B: v2 head reduce + sigmoid (o fastest)
#pragma unroll
            for (int i = 0; i < 4; i++) {
                int e = tid + 256 * i;
                int o = e & 127, b = e >> 7;
                size_t row = (size_t)(B0 + b) * NT + t - 1;
                float s = __ldcg(&g_pre2[row * 512 + o]);
#pragma unroll
                for (int q = 0; q < 16; q++)
                    s += __ldcg(&g_Bv[(((par1 * NGRP + g) * 16 + q) * 8 + b) * 128 + o]);
                s = sigmoid_fast(s);
                if ((o >> 3) == j)
                    __stcg(&out[row * 512 + o], s);
                sMem[(128 + o) * 8 + b] = s;
            }
        }
        __syncthreads();
        // At2 mem-part logging (own 16-m slice, m fastest per b)
        if (tid < 128) {
            int b = tid >> 4, mi = tid & 15;
            int ml = j * 16 + mi;
            float x = sMem[ml * 8 + b];
            __nv_bfloat16 h = __float2bfloat16(x);
            __nv_bfloat16 l = __float2bfloat16(x - __bfloat162float(h));
            size_t base = ((size_t)(B0 + b) * NT + t) * 2560;
            g_At2[base + 1024 + ml] = h;
            g_At2[base + 2304 + ml] = l;
        }
        // ===== 2) GEMM1: v1 slice [64h x 8b] over K=256, warp K-split =====
        {
            float acc[16] = {};
            const int mBase = warp * 32;
#pragma unroll 8
            for (int mm = 0; mm < 32; mm++) {
                int m = mBase + mm;
                float2 wv = *(float2*)&sWm1[m * 64 + lane * 2];
                float4 x0 = *(float4*)&sMem[m * 8];
                float4 x1 = *(float4*)&sMem[m * 8 + 4];
                acc[0] += wv.x * x0.x; acc[1] += wv.x * x0.y; acc[2] += wv.x * x0.z; acc[3] += wv.x * x0.w;
                acc[4] += wv.x * x1.x; acc[5] += wv.x * x1.y; acc[6] += wv.x * x1.z; acc[7] += wv.x * x1.w;
                acc[8]  += wv.y * x0.x; acc[9]  += wv.y * x0.y; acc[10] += wv.y * x0.z; acc[11] += wv.y * x0.w;
                acc[12] += wv.y * x1.x; acc[13] += wv.y * x1.y; acc[14] += wv.y * x1.z; acc[15] += wv.y * x1.w;
            }
#pragma unroll
            for (int hh = 0; hh < 2; hh++) {
                int base = warp * 512 + (lane * 2 + hh) * 8;
                *(float4*)&sRd[base]     = make_float4(acc[hh * 8 + 0], acc[hh * 8 + 1], acc[hh * 8 + 2], acc[hh * 8 + 3]);
                *(float4*)&sRd[base + 4] = make_float4(acc[hh * 8 + 4], acc[hh * 8 + 5], acc[hh * 8 + 6], acc[hh * 8 + 7]);
            }
        }
        __syncthreads();
        // ===== 3) reduce + activation (h fastest -> coalesced pre1 reads) =====
#pragma unroll
        for (int i = 0; i < 2; i++) {
            int idx = tid + 256 * i;
            int h = idx & 63, b = idx >> 6;
            int e = h * 8 + b;
            float s = sRd[e] + sRd[512 + e] + sRd[1024 + e] + sRd[1536 + e]
                    + sRd[2048 + e] + sRd[2560 + e] + sRd[3072 + e] + sRd[3584 + e];
            int hg = j * 64 + h;
            size_t row = (size_t)(B0 + b) * NT + t;
            s += __ldcg(&g_pre1[row * 1024 + hg]);
            s = (hg < 512) ? tanh_fast(s) : fmaxf(s, 0.f);
            sV[e] = s;
        }
        __syncthreads();
        // ===== 3b) coalesced writers: At2 v1-part + v1Tn head =====
        {
            int b = tid >> 5, hp = tid & 31;
            int h2 = hp * 2;
            float s0 = sV[h2 * 8 + b];
            float s1 = sV[(h2 + 1) * 8 + b];
            __nv_bfloat162 hh, ll;
            hh.x = __float2bfloat16(s0); hh.y = __float2bfloat16(s1);
            ll.x = __float2bfloat16(s0 - __bfloat162float(hh.x));
            ll.y = __float2bfloat16(s1 - __bfloat162float(hh.y));
            size_t base = ((size_t)(B0 + b) * NT + t) * 2560;
            *(__nv_bfloat162*)&g_At2[base + j * 64 + h2] = hh;
            *(__nv_bfloat162*)&g_At2[base + 1280 + j * 64 + h2] = ll;
            if (j < 2)
                *(float2*)&g_v1Tn[((par0 * NGRP + g) * 8 + b) * 128 + j * 64 + h2] =
                    make_float2(s0, s1);
        }
        // ===== 4) GEMM2: Bv_j[128o x 8b], coalesced o-fastest stores =====
        {
            const int b = tid >> 5, o4 = (tid & 31) * 4;
            float a0 = 0.f, a1 = 0.f, a2 = 0.f, a3 = 0.f;
#pragma unroll 8
            for (int k = 0; k < 64; k++) {
                float4 wv = *(float4*)&sWB[k * 128 + o4];
                float x = sV[k * 8 + b];
                a0 += wv.x * x; a1 += wv.y * x; a2 += wv.z * x; a3 += wv.w * x;
            }
#pragma unroll
            for (int k = 0; k < 16; k++) {
                float4 wv = *(float4*)&sWB[(64 + k) * 128 + o4];
                float x = sMem[(j * 16 + k) * 8 + b];
                a0 += wv.x * x; a1 += wv.y * x; a2 += wv.z * x; a3 += wv.w * x;
            }
            size_t ob = (size_t)(((par0 * NGRP + g) * 16 + j) * 8 + b) * 128 + o4;
            __stcg((float4*)&g_Bv[ob], make_float4(a0, a1, a2, a3));
        }
        // ===== 5) group barrier =====
        __syncthreads();
        if (tid == 0) {
            __threadfence();
            atomicAdd(cnt, 1u);
            while (*(volatile unsigned*)cnt < tgt) { }
        }
        __syncthreads();
        tgt += GBLK;
    }

    // ===== epilogue: out head for t = NT-1 =====
    {
        const int parL = (NT - 1) & 1;
        if (tid < 64) {
            int o = j * 8 + (tid >> 3), b = tid & 7;
            size_t row = (size_t)(B0 + b) * NT + NT - 1;
            float s = __ldcg(&g_pre2[row * 512 + o]);
#pragma unroll
            for (int q = 0; q < 16; q++)
                s += __ldcg(&g_Bv[(((parL * NGRP + g) * 16 + q) * 8 + b) * 128 + o]);
            s = sigmoid_fast(s);
            __stcg(&out[row * 512 + o], s);
        }
    }
}

// ---------------- launch ----------------
extern "C" void kernel_launch(void* const* d_in, const int* in_sizes, int n_in,
                              void* d_out, int out_size) {
    const float* X   = (const float*)d_in[0];
    const float* mem = (const float*)d_in[1];
    const float* W01 = (const float*)d_in[2];
    const float* b01 = (const float*)d_in[3];
    const float* W02 = (const float*)d_in[4];
    const float* b02 = (const float*)d_in[5];
    const float* W12 = (const float*)d_in[6];
    const float* b12 = (const float*)d_in[7];
    const float* Wm1 = (const float*)d_in[8];
    const float* bm1 = (const float*)d_in[9];
    const float* Wm2 = (const float*)d_in[10];
    const float* bm2 = (const float*)d_in[11];
    float* out = (float*)d_out;

    float *pre1, *pre2, *b1, *b2;
    __nv_bfloat16 *X2, *W013, *W023, *Wt3, *At2;
    cudaGetSymbolAddress((void**)&pre1, g_pre1);
    cudaGetSymbolAddress((void**)&pre2, g_pre2);
    cudaGetSymbolAddress((void**)&b1, g_bias1);
    cudaGetSymbolAddress((void**)&b2, g_bias2);
    cudaGetSymbolAddress((void**)&X2, g_X2);
    cudaGetSymbolAddress((void**)&W013, g_W013);
    cudaGetSymbolAddress((void**)&W023, g_W023);
    cudaGetSymbolAddress((void**)&Wt3, g_Wt3);
    cudaGetSymbolAddress((void**)&At2, g_At2);

    const int HG_SMEM = STG * 128 * 40 * 2 * (int)sizeof(__nv_bfloat16);
    cudaFuncSetAttribute(hgemm_kernel, cudaFuncAttributeMaxDynamicSharedMemorySize, HG_SMEM);
    cudaFuncSetAttribute(loop_kernel, cudaFuncAttributeMaxDynamicSharedMemorySize,
                         STOT * (int)sizeof(float));

    prep_all<<<2048, 256>>>(b01, bm1, b02, b12, bm2, mem, X, W01, W02, W12, Wm2);
    hgemm_kernel<<<dim3(8, NROWS / 128), 256, HG_SMEM>>>(X2, 1024, 16, W013, 1536,
                                                         pre1, 1024, b1, nullptr, 0);
    hgemm_kernel<<<dim3(4, NROWS / 128), 256, HG_SMEM>>>(X2, 1024, 16, W023, 1536,
                                                         pre2, 512, b2, nullptr, 0);
    loop_kernel<<<NGRP * GBLK, 256, STOT * sizeof(float)>>>(Wm1, W12, Wm2, out);
    hgemm_kernel<<<dim3(3, NROWS / 128), 256, HG_SMEM>>>(At2, 2560, 40, Wt3, 3840,
                                                         out + 128, 512, nullptr,
                                                         pre2 + 128, 512);
}

// round 15
// speedup vs baseline: 1.8788x; 1.2005x over previous
#include <cuda_runtime.h>
#include <cuda_bf16.h>
#include <cstdint>
#include <math.h>

#define NBATCH 64
#define NT     512
#define NROWS  (NBATCH * NT)
#define NGRP   8          // batch groups
#define GB     8          // batch per group
#define GBLK   16         // blocks per group

// ---------------- device scratch ----------------
__device__ float g_pre1[NROWS * 1024];
__device__ float g_pre2[NROWS * 512];
__device__ float g_v1Tn[2 * NGRP * 8 * 128];       // [par][g][b][h<128]
__device__ float g_Bv[2 * NGRP * 16 * 8 * 128];    // [par][g][j][b][o]
__device__ float g_mem0T[256 * 64];                // initial memory [m][b]
__device__ float g_bias1[1024];
__device__ float g_bias2[512];
__device__ unsigned g_cnt[NGRP * 32];              // per-group barrier counters, padded
// bf16 split operands (K-concat, deduped hi)
__device__ __nv_bfloat16 g_X2[NROWS * 1024];       // [Xh|Xl]
__device__ __nv_bfloat16 g_W013[1024 * 1536];      // [Wh|Wl|Wh]
__device__ __nv_bfloat16 g_W023[512 * 1536];
__device__ __nv_bfloat16 g_Wt3[384 * 3840];        // [Wh|Wl|Wh] over K=1280
__device__ __nv_bfloat16 g_At2[NROWS * 2560];      // [v1h|memh | v1l|meml], filled by loop

__device__ __forceinline__ float sigmoid_fast(float x) {
    return 1.f / (1.f + __expf(-x));
}
__device__ __forceinline__ float tanh_fast(float x) {
    float e = __expf(2.f * x);
    return 1.f - 2.f / (e + 1.f);
}

// ---------------- fused prep ----------------
__global__ void prep_all(const float* __restrict__ b01, const float* __restrict__ bm1,
                         const float* __restrict__ b02, const float* __restrict__ b12,
                         const float* __restrict__ bm2, const float* __restrict__ memory,
                         const float* __restrict__ X, const float* __restrict__ W01,
                         const float* __restrict__ W02, const float* __restrict__ W12,
                         const float* __restrict__ Wm2) {
    const int gid = blockIdx.x * blockDim.x + threadIdx.x;
    const int n = gridDim.x * blockDim.x;
    if (gid < NGRP) g_cnt[gid * 32] = 0u;
    for (int i = gid; i < 1024; i += n) g_bias1[i] = b01[i] + bm1[i];
    for (int i = gid; i < 512; i += n) g_bias2[i] = b02[i] + b12[i] + bm2[i];
    for (int i = gid; i < 256 * 64; i += n) {
        int m = i >> 6, b = i & 63;
        g_mem0T[i] = memory[b * 256 + m];
    }
    for (int i = gid; i < NROWS * 512; i += n) {
        int r = i >> 9, k = i & 511;
        float x = X[i];
        __nv_bfloat16 h = __float2bfloat16(x);
        __nv_bfloat16 l = __float2bfloat16(x - __bfloat162float(h));
        __nv_bfloat16* d = g_X2 + (size_t)r * 1024 + k;
        d[0] = h; d[512] = l;
    }
    for (int i = gid; i < 1024 * 512; i += n) {
        int r = i >> 9, k = i & 511;
        float x = W01[i];
        __nv_bfloat16 h = __float2bfloat16(x);
        __nv_bfloat16 l = __float2bfloat16(x - __bfloat162float(h));
        __nv_bfloat16* d = g_W013 + (size_t)r * 1536 + k;
        d[0] = h; d[512] = l; d[1024] = h;
    }
    for (int i = gid; i < 512 * 512; i += n) {
        int r = i >> 9, k = i & 511;
        float x = W02[i];
        __nv_bfloat16 h = __float2bfloat16(x);
        __nv_bfloat16 l = __float2bfloat16(x - __bfloat162float(h));
        __nv_bfloat16* d = g_W023 + (size_t)r * 1536 + k;
        d[0] = h; d[512] = l; d[1024] = h;
    }
    for (int i = gid; i < 384 * 1280; i += n) {
        int o = i / 1280, k = i % 1280;
        float x = (k < 1024) ? W12[(o + 128) * 1024 + k] : Wm2[(o + 128) * 256 + (k - 1024)];
        __nv_bfloat16 h = __float2bfloat16(x);
        __nv_bfloat16 l = __float2bfloat16(x - __bfloat162float(h));
        __nv_bfloat16* d = g_Wt3 + (size_t)o * 3840 + k;
        d[0] = h; d[1280] = l; d[2560] = h;
    }
}

// ---------------- bf16 tensor-core GEMM, 3-stage cp.async, wrap-dedup A ----------------
#define STG 3

__device__ __forceinline__ void cp16(uint32_t s, const void* g) {
    asm volatile("cp.async.cg.shared.global [%0], [%1], 16;" :: "r"(s), "l"(g));
}

__global__ void __launch_bounds__(256) hgemm_kernel(const __nv_bfloat16* __restrict__ A,
                                                    int lda, int aHalf,
                                                    const __nv_bfloat16* __restrict__ W, int K,
                                                    float* __restrict__ C, int ldc,
                                                    const float* __restrict__ bias,
                                                    const float* __restrict__ addm, int addld) {
    extern __shared__ __nv_bfloat16 hsm[];
    __nv_bfloat16 (*sA)[128][40] = (__nv_bfloat16(*)[128][40])hsm;
    __nv_bfloat16 (*sW)[128][40] = (__nv_bfloat16(*)[128][40])(hsm + STG * 128 * 40);
    const int tid = threadIdx.x;
    const int n0 = blockIdx.x * 128, m0 = blockIdx.y * 128;
    const int warp = tid >> 5, lane = tid & 31;
    const int wm = (warp >> 1) * 32, wn = (warp & 1) * 64;
    const int lr = tid >> 1, lc = (tid & 1) * 16;
    float acc[2][8][4] = {};
    const __nv_bfloat16* Ag = A + (size_t)(m0 + lr) * lda + lc;
    const __nv_bfloat16* Wg = W + (size_t)(n0 + lr) * K + lc;
    uint32_t aAddr[STG], wAddr[STG];
#pragma unroll
    for (int s = 0; s < STG; s++) {
        aAddr[s] = (uint32_t)__cvta_generic_to_shared(&sA[s][lr][lc]);
        wAddr[s] = (uint32_t)__cvta_generic_to_shared(&sW[s][lr][lc]);
    }
    const int nsteps = K / 32;
#define HG_ISSUE(s) do { \
        int _st = (s) % STG; \
        int _sa = (aHalf && (s) >= aHalf) ? (s) - aHalf : (s); \
        const __nv_bfloat16* _ap = Ag + (size_t)_sa * 32; \
        const __nv_bfloat16* _wp = Wg + (size_t)(s) * 32; \
        cp16(aAddr[_st], _ap); cp16(aAddr[_st] + 16, _ap + 8); \
        cp16(wAddr[_st], _wp); cp16(wAddr[_st] + 16, _wp + 8); \
        asm volatile("cp.async.commit_group;"); \
    } while (0)
    HG_ISSUE(0);
    HG_ISSUE(1);
    asm volatile("cp.async.wait_group 1;");
    __syncthreads();
    for (int s = 0; s < nsteps; s++) {
        if (s + 2 < nsteps) HG_ISSUE(s + 2);
        const int cur = s % STG;
#pragma unroll
        for (int kf = 0; kf < 2; kf++) {
            const int acol = kf * 16 + (lane & 3) * 2;
            const int arow = wm + (lane >> 2);
            uint32_t af[2][4], bfr[8][2];
#pragma unroll
            for (int mi = 0; mi < 2; mi++) {
                af[mi][0] = *(uint32_t*)&sA[cur][arow + mi * 16][acol];
                af[mi][1] = *(uint32_t*)&sA[cur][arow + mi * 16 + 8][acol];
                af[mi][2] = *(uint32_t*)&sA[cur][arow + mi * 16][acol + 8];
                af[mi][3] = *(uint32_t*)&sA[cur][arow + mi * 16 + 8][acol + 8];
            }
#pragma unroll
            for (int ni = 0; ni < 8; ni++) {
                bfr[ni][0] = *(uint32_t*)&sW[cur][wn + ni * 8 + (lane >> 2)][acol];
                bfr[ni][1] = *(uint32_t*)&sW[cur][wn + ni * 8 + (lane >> 2)][acol + 8];
            }
#pragma unroll
            for (int mi = 0; mi < 2; mi++)
#pragma unroll
                for (int ni = 0; ni < 8; ni++)
                    asm volatile(
                        "mma.sync.aligned.m16n8k16.row.col.f32.bf16.bf16.f32 "
                        "{%0,%1,%2,%3}, {%4,%5,%6,%7}, {%8,%9}, {%0,%1,%2,%3};"
                        : "+f"(acc[mi][ni][0]), "+f"(acc[mi][ni][1]),
                          "+f"(acc[mi][ni][2]), "+f"(acc[mi][ni][3])
                        : "r"(af[mi][0]), "r"(af[mi][1]), "r"(af[mi][2]), "r"(af[mi][3]),
                          "r"(bfr[ni][0]), "r"(bfr[ni][1]));
        }
        asm volatile("cp.async.wait_group 1;");
        __syncthreads();
    }
    const int r0 = lane >> 2, c0 = (lane & 3) * 2;
#pragma unroll
    for (int mi = 0; mi < 2; mi++)
#pragma unroll
        for (int ni = 0; ni < 8; ni++) {
            int gr = m0 + wm + mi * 16 + r0;
            int gcg = n0 + wn + ni * 8 + c0;
            float v0 = acc[mi][ni][0], v1 = acc[mi][ni][1];
            float v2 = acc[mi][ni][2], v3 = acc[mi][ni][3];
            if (bias) {
                float2 bb = *(const float2*)&bias[gcg];
                v0 += bb.x; v1 += bb.y; v2 += bb.x; v3 += bb.y;
            }
            if (addm) {
                float2 a0 = *(const float2*)&addm[(size_t)gr * addld + gcg];
                float2 a1 = *(const float2*)&addm[(size_t)(gr + 8) * addld + gcg];
                v0 += a0.x; v1 += a0.y; v2 += a1.x; v3 += a1.y;
            }
            *(float2*)&C[(size_t)gr * ldc + gcg] = make_float2(v0, v1);
            *(float2*)&C[(size_t)(gr + 8) * ldc + gcg] = make_float2(v2, v3);
        }
}

// ---------------- one-barrier loop, register-cached GEMM2 weights ----------------
// smem layout (floats):
#define SWM1  0          // [256m][64h]   Wm1 slice               16384
#define SRD   16384      // scratch: GEMM1 partials (4096) / GEMM2 partials [w][b][o] (8192)
#define SMEM  24576      // [256m][8b]                             2048
#define SV    26624      // [64h][8b]                               512
#define STOT  27136

__global__ void __launch_bounds__(256, 1) loop_kernel(const float* __restrict__ Wm1,
                                                      const float* __restrict__ W12,
                                                      const float* __restrict__ Wm2,
                                                      float* __restrict__ out) {
    extern __shared__ float sm[];
    float* sWm1 = sm + SWM1;
    float* sRd  = sm + SRD;
    float* sMem = sm + SMEM;
    float* sV   = sm + SV;

    const int tid = threadIdx.x;
    const int g   = blockIdx.x >> 4;
    const int j   = blockIdx.x & 15;
    const int B0  = g * GB;
    const int warp = tid >> 5, lane = tid & 31;
    const int o4 = lane * 4;

    // one-time Wm1 staging
    for (int i = tid; i < 64 * 256; i += 256) {        // sWm1[m][h]
        int m = i >> 6, h = i & 63;
        sWm1[m * 64 + h] = Wm1[(j * 64 + h) * 256 + m];
    }
    // one-time GEMM2 weight registers: warp k-split (10 k), lane -> o4
    float4 wr[10];
#pragma unroll
    for (int kk = 0; kk < 10; kk++) {
        int k = warp * 10 + kk;
        float w[4];
#pragma unroll
        for (int i = 0; i < 4; i++) {
            int o = o4 + i;
            w[i] = (k < 64) ? W12[o * 1024 + j * 64 + k]
                            : Wm2[o * 256 + j * 16 + (k - 64)];
        }
        wr[kk] = make_float4(w[0], w[1], w[2], w[3]);
    }
    __syncthreads();

    unsigned tgt = GBLK;
    unsigned* cnt = &g_cnt[g * 32];
    float p2v[4];   // prefetched pre2 for next step's assemble

    for (int t = 0; t < NT; t++) {
        const int par0 = t & 1, par1 = par0 ^ 1;
        // prefetch pre1 for this step (consumed in stage 3; latency hidden by GEMM1)
        float p1v[2];
#pragma unroll
        for (int i = 0; i < 2; i++) {
            int idx = tid + 256 * i;
            int h = idx & 63, b = idx >> 6;
            p1v[i] = __ldcg(&g_pre1[((size_t)(B0 + b) * NT + t) * 1024 + j * 64 + h]);
        }
        // ===== 1) assemble mem[256m][8b] =====
        if (t == 0) {
#pragma unroll
            for (int i = 0; i < 8; i++) {
                int e = tid + 256 * i;
                int m = e >> 3, b = e & 7;
                sMem[e] = g_mem0T[m * 64 + B0 + b];
            }
        } else {
#pragma unroll
            for (int i = 0; i < 4; i++) {
                int e = tid + 256 * i;
                int h = e & 127, b = e >> 7;
                sMem[h * 8 + b] = __ldcg(&g_v1Tn[((par1 * NGRP + g) * 8 + b) * 128 + h]);
            }
#pragma unroll
            for (int i = 0; i < 4; i++) {
                int e = tid + 256 * i;
                int o = e & 127, b = e >> 7;
                size_t row = (size_t)(B0 + b) * NT + t - 1;
                float s = p2v[i];
#pragma unroll
                for (int q = 0; q < 16; q++)
                    s += __ldcg(&g_Bv[(((par1 * NGRP + g) * 16 + q) * 8 + b) * 128 + o]);
                s = sigmoid_fast(s);
                if ((o >> 3) == j)
                    __stcg(&out[row * 512 + o], s);
                sMem[(128 + o) * 8 + b] = s;
            }
        }
        __syncthreads();
        // At2 mem-part logging (own 16-m slice)
        if (tid < 128) {
            int b = tid >> 4, mi = tid & 15;
            int ml = j * 16 + mi;
            float x = sMem[ml * 8 + b];
            __nv_bfloat16 h = __float2bfloat16(x);
            __nv_bfloat16 l = __float2bfloat16(x - __bfloat162float(h));
            size_t base = ((size_t)(B0 + b) * NT + t) * 2560;
            g_At2[base + 1024 + ml] = h;
            g_At2[base + 2304 + ml] = l;
        }
        // ===== 2) GEMM1: v1 slice [64h x 8b] over K=256, warp K-split =====
        {
            float acc[16] = {};
            const int mBase = warp * 32;
#pragma unroll 8
            for (int mm = 0; mm < 32; mm++) {
                int m = mBase + mm;
                float2 wv = *(float2*)&sWm1[m * 64 + lane * 2];
                float4 x0 = *(float4*)&sMem[m * 8];
                float4 x1 = *(float4*)&sMem[m * 8 + 4];
                acc[0] += wv.x * x0.x; acc[1] += wv.x * x0.y; acc[2] += wv.x * x0.z; acc[3] += wv.x * x0.w;
                acc[4] += wv.x * x1.x; acc[5] += wv.x * x1.y; acc[6] += wv.x * x1.z; acc[7] += wv.x * x1.w;
                acc[8]  += wv.y * x0.x; acc[9]  += wv.y * x0.y; acc[10] += wv.y * x0.z; acc[11] += wv.y * x0.w;
                acc[12] += wv.y * x1.x; acc[13] += wv.y * x1.y; acc[14] += wv.y * x1.z; acc[15] += wv.y * x1.w;
            }
#pragma unroll
            for (int hh = 0; hh < 2; hh++) {
                int base = warp * 512 + (lane * 2 + hh) * 8;
                *(float4*)&sRd[base]     = make_float4(acc[hh * 8 + 0], acc[hh * 8 + 1], acc[hh * 8 + 2], acc[hh * 8 + 3]);
                *(float4*)&sRd[base + 4] = make_float4(acc[hh * 8 + 4], acc[hh * 8 + 5], acc[hh * 8 + 6], acc[hh * 8 + 7]);
            }
        }
        __syncthreads();
        // ===== 3) reduce + activation (uses prefetched pre1) =====
#pragma unroll
        for (int i = 0; i < 2; i++) {
            int idx = tid + 256 * i;
            int h = idx & 63, b = idx >> 6;
            int e = h * 8 + b;
            float s = sRd[e] + sRd[512 + e] + sRd[1024 + e] + sRd[1536 + e]
                    + sRd[2048 + e] + sRd[2560 + e] + sRd[3072 + e] + sRd[3584 + e];
            int hg = j * 64 + h;
            s += p1v[i];
            s = (hg < 512) ? tanh_fast(s) : fmaxf(s, 0.f);
            sV[e] = s;
        }
        __syncthreads();
        // ===== 3b) coalesced writers: At2 v1-part + v1Tn head =====
        {
            int b = tid >> 5, hp = tid & 31;
            int h2 = hp * 2;
            float s0 = sV[h2 * 8 + b];
            float s1 = sV[(h2 + 1) * 8 + b];
            __nv_bfloat162 hh, ll;
            hh.x = __float2bfloat16(s0); hh.y = __float2bfloat16(s1);
            ll.x = __float2bfloat16(s0 - __bfloat162float(hh.x));
            ll.y = __float2bfloat16(s1 - __bfloat162float(hh.y));
            size_t base = ((size_t)(B0 + b) * NT + t) * 2560;
            *(__nv_bfloat162*)&g_At2[base + j * 64 + h2] = hh;
            *(__nv_bfloat162*)&g_At2[base + 1280 + j * 64 + h2] = ll;
            if (j < 2)
                *(float2*)&g_v1Tn[((par0 * NGRP + g) * 8 + b) * 128 + j * 64 + h2] =
                    make_float2(s0, s1);
        }
        // ===== 4) GEMM2: register weights, warp k-split; partials [w][b][o] =====
        {
            float acc2[4][8];
#pragma unroll
            for (int i = 0; i < 4; i++)
#pragma unroll
                for (int b = 0; b < 8; b++) acc2[i][b] = 0.f;
#pragma unroll
            for (int kk = 0; kk < 10; kk++) {
                int k = warp * 10 + kk;
                const float* xb = (k < 64) ? &sV[k * 8] : &sMem[(j * 16 + (k - 64)) * 8];
                float4 x0 = *(float4*)xb;
                float4 x1 = *(float4*)(xb + 4);
                float xv[8] = {x0.x, x0.y, x0.z, x0.w, x1.x, x1.y, x1.z, x1.w};
                float wv[4] = {wr[kk].x, wr[kk].y, wr[kk].z, wr[kk].w};
#pragma unroll
                for (int i = 0; i < 4; i++)
#pragma unroll
                    for (int b = 0; b < 8; b++) acc2[i][b] += wv[i] * xv[b];
            }
#pragma unroll
            for (int b = 0; b < 8; b++)
                *(float4*)&sRd[(warp * 8 + b) * 128 + o4] =
                    make_float4(acc2[0][b], acc2[1][b], acc2[2][b], acc2[3][b]);
        }
        __syncthreads();
        // ===== 4b) reduce partials across warps, coalesced Bv store =====
        {
            int rb = tid >> 5, ro4 = (tid & 31) * 4;
            float4 s = *(float4*)&sRd[(0 * 8 + rb) * 128 + ro4];
#pragma unroll
            for (int w = 1; w < 8; w++) {
                float4 p = *(float4*)&sRd[(w * 8 + rb) * 128 + ro4];
                s.x += p.x; s.y += p.y; s.z += p.z; s.w += p.w;
            }
            size_t ob = (size_t)(((par0 * NGRP + g) * 16 + j) * 8 + rb) * 128 + ro4;
            __stcg((float4*)&g_Bv[ob], s);
        }
        // prefetch pre2 for next step's assemble (row t)
        if (t + 1 < NT) {
#pragma unroll
            for (int i = 0; i < 4; i++) {
                int e = tid + 256 * i;
                int o = e & 127, b = e >> 7;
                p2v[i] = __ldcg(&g_pre2[((size_t)(B0 + b) * NT + t) * 512 + o]);
            }
        }
        // ===== 5) group barrier =====
        __syncthreads();
        if (tid == 0) {
            __threadfence();
            atomicAdd(cnt, 1u);
            while (*(volatile unsigned*)cnt < tgt) { }
        }
        __syncthreads();
        tgt += GBLK;
    }

    // ===== epilogue: out head for t = NT-1 =====
    {
        const int parL = (NT - 1) & 1;
        if (tid < 64) {
            int o = j * 8 + (tid >> 3), b = tid & 7;
            size_t row = (size_t)(B0 + b) * NT + NT - 1;
            float s = __ldcg(&g_pre2[row * 512 + o]);
#pragma unroll
            for (int q = 0; q < 16; q++)
                s += __ldcg(&g_Bv[(((parL * NGRP + g) * 16 + q) * 8 + b) * 128 + o]);
            s = sigmoid_fast(s);
            __stcg(&out[row * 512 + o], s);
        }
    }
}

// ---------------- launch ----------------
extern "C" void kernel_launch(void* const* d_in, const int* in_sizes, int n_in,
                              void* d_out, int out_size) {
    const float* X   = (const float*)d_in[0];
    const float* mem = (const float*)d_in[1];
    const float* W01 = (const float*)d_in[2];
    const float* b01 = (const float*)d_in[3];
    const float* W02 = (const float*)d_in[4];
    const float* b02 = (const float*)d_in[5];
    const float* W12 = (const float*)d_in[6];
    const float* b12 = (const float*)d_in[7];
    const float* Wm1 = (const float*)d_in[8];
    const float* bm1 = (const float*)d_in[9];
    const float* Wm2 = (const float*)d_in[10];
    const float* bm2 = (const float*)d_in[11];
    float* out = (float*)d_out;

    float *pre1, *pre2, *b1, *b2;
    __nv_bfloat16 *X2, *W013, *W023, *Wt3, *At2;
    cudaGetSymbolAddress((void**)&pre1, g_pre1);
    cudaGetSymbolAddress((void**)&pre2, g_pre2);
    cudaGetSymbolAddress((void**)&b1, g_bias1);
    cudaGetSymbolAddress((void**)&b2, g_bias2);
    cudaGetSymbolAddress((void**)&X2, g_X2);
    cudaGetSymbolAddress((void**)&W013, g_W013);
    cudaGetSymbolAddress((void**)&W023, g_W023);
    cudaGetSymbolAddress((void**)&Wt3, g_Wt3);
    cudaGetSymbolAddress((void**)&At2, g_At2);

    const int HG_SMEM = STG * 128 * 40 * 2 * (int)sizeof(__nv_bfloat16);
    cudaFuncSetAttribute(hgemm_kernel, cudaFuncAttributeMaxDynamicSharedMemorySize, HG_SMEM);
    cudaFuncSetAttribute(loop_kernel, cudaFuncAttributeMaxDynamicSharedMemorySize,
                         STOT * (int)sizeof(float));

    prep_all<<<2048, 256>>>(b01, bm1, b02, b12, bm2, mem, X, W01, W02, W12, Wm2);
    hgemm_kernel<<<dim3(8, NROWS / 128), 256, HG_SMEM>>>(X2, 1024, 16, W013, 1536,
                                                         pre1, 1024, b1, nullptr, 0);
    hgemm_kernel<<<dim3(4, NROWS / 128), 256, HG_SMEM>>>(X2, 1024, 16, W023, 1536,
                                                         pre2, 512, b2, nullptr, 0);
    loop_kernel<<<NGRP * GBLK, 256, STOT * sizeof(float)>>>(Wm1, W12, Wm2, out);
    hgemm_kernel<<<dim3(3, NROWS / 128), 256, HG_SMEM>>>(At2, 2560, 40, Wt3, 3840,
                                                         out + 128, 512, nullptr,
                                                         pre2 + 128, 512);
}

// round 16
// speedup vs baseline: 2.1965x; 1.1691x over previous
#include <cuda_runtime.h>
#include <cuda_bf16.h>
#include <cstdint>
#include <math.h>

#define NBATCH 64
#define NT     512
#define NROWS  (NBATCH * NT)
#define NGRP   8          // batch groups
#define GB     8          // batch per group
#define GBLK   16         // blocks per group

// ---------------- device scratch ----------------
__device__ float g_pre1[NROWS * 1024];
__device__ float g_pre2[NROWS * 512];
__device__ float g_v1Tn[2 * NGRP * 8 * 128];       // [par][g][b][h<128]
__device__ float g_Bv[2 * NGRP * 16 * 8 * 128];    // [par][g][j][b][o]
__device__ float g_mem0T[256 * 64];                // initial memory [m][b]
__device__ float g_bias1[1024];
__device__ float g_bias2[512];
__device__ unsigned g_cnt[NGRP * 32];              // per-group barrier counters, padded
// bf16 split operands
__device__ __nv_bfloat16 g_X2[NROWS * 1024];       // [Xh|Xl]
__device__ __nv_bfloat16 g_W013[1024 * 1536];      // [Wh|Wl|Wh]
__device__ __nv_bfloat16 g_W023[512 * 1536];
__device__ __nv_bfloat16 g_Wt3[384 * 3840];        // [Wh|Wl|Wh] over K=1280
__device__ __nv_bfloat16 g_Wm1b[1024 * 512];       // Wm1 [Wh|Wl] per row (for loop mma)
__device__ __nv_bfloat16 g_At2[NROWS * 2560];      // [v1h|memh | v1l|meml], filled by loop

__device__ __forceinline__ float sigmoid_fast(float x) {
    return 1.f / (1.f + __expf(-x));
}
__device__ __forceinline__ float tanh_fast(float x) {
    float e = __expf(2.f * x);
    return 1.f - 2.f / (e + 1.f);
}

// ---------------- fused prep ----------------
__global__ void prep_all(const float* __restrict__ b01, const float* __restrict__ bm1,
                         const float* __restrict__ b02, const float* __restrict__ b12,
                         const float* __restrict__ bm2, const float* __restrict__ memory,
                         const float* __restrict__ X, const float* __restrict__ W01,
                         const float* __restrict__ W02, const float* __restrict__ W12,
                         const float* __restrict__ Wm1, const float* __restrict__ Wm2) {
    const int gid = blockIdx.x * blockDim.x + threadIdx.x;
    const int n = gridDim.x * blockDim.x;
    if (gid < NGRP) g_cnt[gid * 32] = 0u;
    for (int i = gid; i < 1024; i += n) g_bias1[i] = b01[i] + bm1[i];
    for (int i = gid; i < 512; i += n) g_bias2[i] = b02[i] + b12[i] + bm2[i];
    for (int i = gid; i < 256 * 64; i += n) {
        int m = i >> 6, b = i & 63;
        g_mem0T[i] = memory[b * 256 + m];
    }
    for (int i = gid; i < NROWS * 512; i += n) {
        int r = i >> 9, k = i & 511;
        float x = X[i];
        __nv_bfloat16 h = __float2bfloat16(x);
        __nv_bfloat16 l = __float2bfloat16(x - __bfloat162float(h));
        __nv_bfloat16* d = g_X2 + (size_t)r * 1024 + k;
        d[0] = h; d[512] = l;
    }
    for (int i = gid; i < 1024 * 512; i += n) {
        int r = i >> 9, k = i & 511;
        float x = W01[i];
        __nv_bfloat16 h = __float2bfloat16(x);
        __nv_bfloat16 l = __float2bfloat16(x - __bfloat162float(h));
        __nv_bfloat16* d = g_W013 + (size_t)r * 1536 + k;
        d[0] = h; d[512] = l; d[1024] = h;
    }
    for (int i = gid; i < 512 * 512; i += n) {
        int r = i >> 9, k = i & 511;
        float x = W02[i];
        __nv_bfloat16 h = __float2bfloat16(x);
        __nv_bfloat16 l = __float2bfloat16(x - __bfloat162float(h));
        __nv_bfloat16* d = g_W023 + (size_t)r * 1536 + k;
        d[0] = h; d[512] = l; d[1024] = h;
    }
    for (int i = gid; i < 384 * 1280; i += n) {
        int o = i / 1280, k = i % 1280;
        float x = (k < 1024) ? W12[(o + 128) * 1024 + k] : Wm2[(o + 128) * 256 + (k - 1024)];
        __nv_bfloat16 h = __float2bfloat16(x);
        __nv_bfloat16 l = __float2bfloat16(x - __bfloat162float(h));
        __nv_bfloat16* d = g_Wt3 + (size_t)o * 3840 + k;
        d[0] = h; d[1280] = l; d[2560] = h;
    }
    // Wm1 bf16 split for in-loop mma: [h][ hi(0..255) | lo(0..255) ]
    for (int i = gid; i < 1024 * 256; i += n) {
        int h = i >> 8, m = i & 255;
        float x = Wm1[h * 256 + m];
        __nv_bfloat16 hh = __float2bfloat16(x);
        __nv_bfloat16 ll = __float2bfloat16(x - __bfloat162float(hh));
        g_Wm1b[(size_t)h * 512 + m] = hh;
        g_Wm1b[(size_t)h * 512 + 256 + m] = ll;
    }
}

// ---------------- bf16 tensor-core GEMM, 3-stage cp.async, wrap-dedup A ----------------
#define STG 3

__device__ __forceinline__ void cp16(uint32_t s, const void* g) {
    asm volatile("cp.async.cg.shared.global [%0], [%1], 16;" :: "r"(s), "l"(g));
}

__global__ void __launch_bounds__(256) hgemm_kernel(const __nv_bfloat16* __restrict__ A,
                                                    int lda, int aHalf,
                                                    const __nv_bfloat16* __restrict__ W, int K,
                                                    float* __restrict__ C, int ldc,
                                                    const float* __restrict__ bias,
                                                    const float* __restrict__ addm, int addld) {
    extern __shared__ __nv_bfloat16 hsm[];
    __nv_bfloat16 (*sA)[128][40] = (__nv_bfloat16(*)[128][40])hsm;
    __nv_bfloat16 (*sW)[128][40] = (__nv_bfloat16(*)[128][40])(hsm + STG * 128 * 40);
    const int tid = threadIdx.x;
    const int n0 = blockIdx.x * 128, m0 = blockIdx.y * 128;
    const int warp = tid >> 5, lane = tid & 31;
    const int wm = (warp >> 1) * 32, wn = (warp & 1) * 64;
    const int lr = tid >> 1, lc = (tid & 1) * 16;
    float acc[2][8][4] = {};
    const __nv_bfloat16* Ag = A + (size_t)(m0 + lr) * lda + lc;
    const __nv_bfloat16* Wg = W + (size_t)(n0 + lr) * K + lc;
    uint32_t aAddr[STG], wAddr[STG];
#pragma unroll
    for (int s = 0; s < STG; s++) {
        aAddr[s] = (uint32_t)__cvta_generic_to_shared(&sA[s][lr][lc]);
        wAddr[s] = (uint32_t)__cvta_generic_to_shared(&sW[s][lr][lc]);
    }
    const int nsteps = K / 32;
#define HG_ISSUE(s) do { \
        int _st = (s) % STG; \
        int _sa = (aHalf && (s) >= aHalf) ? (s) - aHalf : (s); \
        const __nv_bfloat16* _ap = Ag + (size_t)_sa * 32; \
        const __nv_bfloat16* _wp = Wg + (size_t)(s) * 32; \
        cp16(aAddr[_st], _ap); cp16(aAddr[_st] + 16, _ap + 8); \
        cp16(wAddr[_st], _wp); cp16(wAddr[_st] + 16, _wp + 8); \
        asm volatile("cp.async.commit_group;"); \
    } while (0)
    HG_ISSUE(0);
    HG_ISSUE(1);
    asm volatile("cp.async.wait_group 1;");
    __syncthreads();
    for (int s = 0; s < nsteps; s++) {
        if (s + 2 < nsteps) HG_ISSUE(s + 2);
        const int cur = s % STG;
#pragma unroll
        for (int kf = 0; kf < 2; kf++) {
            const int acol = kf * 16 + (lane & 3) * 2;
            const int arow = wm + (lane >> 2);
            uint32_t af[2][4], bfr[8][2];
#pragma unroll
            for (int mi = 0; mi < 2; mi++) {
                af[mi][0] = *(uint32_t*)&sA[cur][arow + mi * 16][acol];
                af[mi][1] = *(uint32_t*)&sA[cur][arow + mi * 16 + 8][acol];
                af[mi][2] = *(uint32_t*)&sA[cur][arow + mi * 16][acol + 8];
                af[mi][3] = *(uint32_t*)&sA[cur][arow + mi * 16 + 8][acol + 8];
            }
#pragma unroll
            for (int ni = 0; ni < 8; ni++) {
                bfr[ni][0] = *(uint32_t*)&sW[cur][wn + ni * 8 + (lane >> 2)][acol];
                bfr[ni][1] = *(uint32_t*)&sW[cur][wn + ni * 8 + (lane >> 2)][acol + 8];
            }
#pragma unroll
            for (int mi = 0; mi < 2; mi++)
#pragma unroll
                for (int ni = 0; ni < 8; ni++)
                    asm volatile(
                        "mma.sync.aligned.m16n8k16.row.col.f32.bf16.bf16.f32 "
                        "{%0,%1,%2,%3}, {%4,%5,%6,%7}, {%8,%9}, {%0,%1,%2,%3};"
                        : "+f"(acc[mi][ni][0]), "+f"(acc[mi][ni][1]),
                          "+f"(acc[mi][ni][2]), "+f"(acc[mi][ni][3])
                        : "r"(af[mi][0]), "r"(af[mi][1]), "r"(af[mi][2]), "r"(af[mi][3]),
                          "r"(bfr[ni][0]), "r"(bfr[ni][1]));
        }
        asm volatile("cp.async.wait_group 1;");
        __syncthreads();
    }
    const int r0 = lane >> 2, c0 = (lane & 3) * 2;
#pragma unroll
    for (int mi = 0; mi < 2; mi++)
#pragma unroll
        for (int ni = 0; ni < 8; ni++) {
            int gr = m0 + wm + mi * 16 + r0;
            int gcg = n0 + wn + ni * 8 + c0;
            float v0 = acc[mi][ni][0], v1 = acc[mi][ni][1];
            float v2 = acc[mi][ni][2], v3 = acc[mi][ni][3];
            if (bias) {
                float2 bb = *(const float2*)&bias[gcg];
                v0 += bb.x; v1 += bb.y; v2 += bb.x; v3 += bb.y;
            }
            if (addm) {
                float2 a0 = *(const float2*)&addm[(size_t)gr * addld + gcg];
                float2 a1 = *(const float2*)&addm[(size_t)(gr + 8) * addld + gcg];
                v0 += a0.x; v1 += a0.y; v2 += a1.x; v3 += a1.y;
            }
            *(float2*)&C[(size_t)gr * ldc + gcg] = make_float2(v0, v1);
            *(float2*)&C[(size_t)(gr + 8) * ldc + gcg] = make_float2(v2, v3);
        }
}

// ---------------- one-barrier loop: tensor-core GEMM1, reg-weight GEMM2 ----------------
// smem layout (floats):
#define SRD   0          // 8192: GEMM2 partials [w][b][o]; GEMM1 partials use first 1024
#define SMEM  8192       // [256m][8b] fp32                 2048
#define SV    10240      // [64h][8b] fp32                   512
#define SB    10752      // bf16 [8b][536]: [mh|ml] cols     2144 floats
#define STOT  12896

__global__ void __launch_bounds__(256, 1) loop_kernel(const float* __restrict__ Wm1,
                                                      const float* __restrict__ W12,
                                                      const float* __restrict__ Wm2,
                                                      float* __restrict__ out) {
    extern __shared__ float sm[];
    float* sRd  = sm + SRD;
    float* sMem = sm + SMEM;
    float* sV   = sm + SV;
    __nv_bfloat16* sB16 = (__nv_bfloat16*)(sm + SB);   // [8][536]

    const int tid = threadIdx.x;
    const int g   = blockIdx.x >> 4;
    const int j   = blockIdx.x & 15;
    const int B0  = g * GB;
    const int warp = tid >> 5, lane = tid & 31;
    const int o4 = lane * 4;
    const int mtile = warp >> 1, kpart = warp & 1;     // GEMM1 roles

    // one-time GEMM1 A-fragments in registers: warp (mtile,kpart), 24 ksteps
    uint32_t areg[24][4];
    {
        int hrow = (j * 64 + mtile * 16 + (lane >> 2));
#pragma unroll
        for (int s = 0; s < 24; s++) {
            int k0 = (kpart * 24 + s) * 16;
            int ka = (k0 < 512) ? k0 : k0 - 512;
            const __nv_bfloat16* base = &g_Wm1b[(size_t)hrow * 512 + ka + (lane & 3) * 2];
            areg[s][0] = *(const uint32_t*)base;
            areg[s][1] = *(const uint32_t*)(base + 8 * 512);
            areg[s][2] = *(const uint32_t*)(base + 8);
            areg[s][3] = *(const uint32_t*)(base + 8 * 512 + 8);
        }
    }
    // one-time GEMM2 weight registers: warp k-split (10 k), lane -> o4
    float4 wr[10];
#pragma unroll
    for (int kk = 0; kk < 10; kk++) {
        int k = warp * 10 + kk;
        float w[4];
#pragma unroll
        for (int i = 0; i < 4; i++) {
            int o = o4 + i;
            w[i] = (k < 64) ? W12[o * 1024 + j * 64 + k]
                            : Wm2[o * 256 + j * 16 + (k - 64)];
        }
        wr[kk] = make_float4(w[0], w[1], w[2], w[3]);
    }
    __syncthreads();

    unsigned tgt = GBLK;
    unsigned* cnt = &g_cnt[g * 32];
    float p2v[4];

    for (int t = 0; t < NT; t++) {
        const int par0 = t & 1, par1 = par0 ^ 1;
        // prefetch pre1 for this step
        float p1v[2];
#pragma unroll
        for (int i = 0; i < 2; i++) {
            int idx = tid + 256 * i;
            int h = idx & 63, b = idx >> 6;
            p1v[i] = __ldcg(&g_pre1[((size_t)(B0 + b) * NT + t) * 1024 + j * 64 + h]);
        }
        // ===== 1) assemble mem[256m][8b] fp32 + sB16 hi/lo =====
        if (t == 0) {
#pragma unroll
            for (int i = 0; i < 8; i++) {
                int e = tid + 256 * i;
                int m = e >> 3, b = e & 7;
                float x = g_mem0T[m * 64 + B0 + b];
                sMem[e] = x;
                __nv_bfloat16 hh = __float2bfloat16(x);
                sB16[b * 536 + m] = hh;
                sB16[b * 536 + 256 + m] = __float2bfloat16(x - __bfloat162float(hh));
            }
        } else {
#pragma unroll
            for (int i = 0; i < 4; i++) {
                int e = tid + 256 * i;
                int h = e & 127, b = e >> 7;
                float x = __ldcg(&g_v1Tn[((par1 * NGRP + g) * 8 + b) * 128 + h]);
                sMem[h * 8 + b] = x;
                __nv_bfloat16 hh = __float2bfloat16(x);
                sB16[b * 536 + h] = hh;
                sB16[b * 536 + 256 + h] = __float2bfloat16(x - __bfloat162float(hh));
            }
#pragma unroll
            for (int i = 0; i < 4; i++) {
                int e = tid + 256 * i;
                int o = e & 127, b = e >> 7;
                size_t row = (size_t)(B0 + b) * NT + t - 1;
                float s = p2v[i];
#pragma unroll
                for (int q = 0; q < 16; q++)
                    s += __ldcg(&g_Bv[(((par1 * NGRP + g) * 16 + q) * 8 + b) * 128 + o]);
                s = sigmoid_fast(s);
                if ((o >> 3) == j)
                    __stcg(&out[row * 512 + o], s);
                int m = 128 + o;
                sMem[m * 8 + b] = s;
                __nv_bfloat16 hh = __float2bfloat16(s);
                sB16[b * 536 + m] = hh;
                sB16[b * 536 + 256 + m] = __float2bfloat16(s - __bfloat162float(hh));
            }
        }
        __syncthreads();
        // At2 mem-part logging (own 16-m slice)
        if (tid < 128) {
            int b = tid >> 4, mi = tid & 15;
            int ml = j * 16 + mi;
            float x = sMem[ml * 8 + b];
            __nv_bfloat16 h = __float2bfloat16(x);
            __nv_bfloat16 l = __float2bfloat16(x - __bfloat162float(h));
            size_t base = ((size_t)(B0 + b) * NT + t) * 2560;
            g_At2[base + 1024 + ml] = h;
            g_At2[base + 2304 + ml] = l;
        }
        // ===== 2) GEMM1 via tensor cores: [64h x 8b], K=768 concat, 2 accumulators =====
        {
            float cA[4] = {}, cB[4] = {};
            const int brow = (lane >> 2) * 536 + (lane & 3) * 2;
#pragma unroll
            for (int s = 0; s < 24; s += 2) {
#pragma unroll
                for (int u = 0; u < 2; u++) {
                    int k0 = (kpart * 24 + s + u) * 16;
                    int kb = (k0 < 256) ? k0 : k0 - 256;
                    uint32_t b0 = *(uint32_t*)&sB16[brow + kb];
                    uint32_t b1 = *(uint32_t*)&sB16[brow + kb + 8];
                    float* cc = u ? cB : cA;
                    asm volatile(
                        "mma.sync.aligned.m16n8k16.row.col.f32.bf16.bf16.f32 "
                        "{%0,%1,%2,%3}, {%4,%5,%6,%7}, {%8,%9}, {%0,%1,%2,%3};"
                        : "+f"(cc[0]), "+f"(cc[1]), "+f"(cc[2]), "+f"(cc[3])
                        : "r"(areg[s + u][0]), "r"(areg[s + u][1]),
                          "r"(areg[s + u][2]), "r"(areg[s + u][3]),
                          "r"(b0), "r"(b1));
                }
            }
            int h_loc = mtile * 16 + (lane >> 2);
            int bc = (lane & 3) * 2;
            sRd[kpart * 512 + h_loc * 8 + bc]           = cA[0] + cB[0];
            sRd[kpart * 512 + h_loc * 8 + bc + 1]       = cA[1] + cB[1];
            sRd[kpart * 512 + (h_loc + 8) * 8 + bc]     = cA[2] + cB[2];
            sRd[kpart * 512 + (h_loc + 8) * 8 + bc + 1] = cA[3] + cB[3];
        }
        __syncthreads();
        // ===== 3) reduce 2 partials + activation =====
#pragma unroll
        for (int i = 0; i < 2; i++) {
            int idx = tid + 256 * i;
            int h = idx & 63, b = idx >> 6;
            int e = h * 8 + b;
            float s = sRd[e] + sRd[512 + e] + p1v[i];
            int hg = j * 64 + h;
            s = (hg < 512) ? tanh_fast(s) : fmaxf(s, 0.f);
            sV[e] = s;
        }
        __syncthreads();
        // ===== 3b) coalesced writers: At2 v1-part + v1Tn head =====
        {
            int b = tid >> 5, hp = tid & 31;
            int h2 = hp * 2;
            float s0 = sV[h2 * 8 + b];
            float s1 = sV[(h2 + 1) * 8 + b];
            __nv_bfloat162 hh, ll;
            hh.x = __float2bfloat16(s0); hh.y = __float2bfloat16(s1);
            ll.x = __float2bfloat16(s0 - __bfloat162float(hh.x));
            ll.y = __float2bfloat16(s1 - __bfloat162float(hh.y));
            size_t base = ((size_t)(B0 + b) * NT + t) * 2560;
            *(__nv_bfloat162*)&g_At2[base + j * 64 + h2] = hh;
            *(__nv_bfloat162*)&g_At2[base + 1280 + j * 64 + h2] = ll;
            if (j < 2)
                *(float2*)&g_v1Tn[((par0 * NGRP + g) * 8 + b) * 128 + j * 64 + h2] =
                    make_float2(s0, s1);
        }
        // ===== 4) GEMM2: register weights, warp k-split; partials [w][b][o] =====
        {
            float acc2[4][8];
#pragma unroll
            for (int i = 0; i < 4; i++)
#pragma unroll
                for (int b = 0; b < 8; b++) acc2[i][b] = 0.f;
#pragma unroll
            for (int kk = 0; kk < 10; kk++) {
                int k = warp * 10 + kk;
                const float* xb = (k < 64) ? &sV[k * 8] : &sMem[(j * 16 + (k - 64)) * 8];
                float4 x0 = *(float4*)xb;
                float4 x1 = *(float4*)(xb + 4);
                float xv[8] = {x0.x, x0.y, x0.z, x0.w, x1.x, x1.y, x1.z, x1.w};
                float wv[4] = {wr[kk].x, wr[kk].y, wr[kk].z, wr[kk].w};
#pragma unroll
                for (int i = 0; i < 4; i++)
#pragma unroll
                    for (int b = 0; b < 8; b++) acc2[i][b] += wv[i] * xv[b];
            }
#pragma unroll
            for (int b = 0; b < 8; b++)
                *(float4*)&sRd[(warp * 8 + b) * 128 + o4] =
                    make_float4(acc2[0][b], acc2[1][b], acc2[2][b], acc2[3][b]);
        }
        __syncthreads();
        // ===== 4b) reduce partials across warps, coalesced Bv store =====
        {
            int rb = tid >> 5, ro4 = (tid & 31) * 4;
            float4 s = *(float4*)&sRd[(0 * 8 + rb) * 128 + ro4];
#pragma unroll
            for (int w = 1; w < 8; w++) {
                float4 p = *(float4*)&sRd[(w * 8 + rb) * 128 + ro4];
                s.x += p.x; s.y += p.y; s.z += p.z; s.w += p.w;
            }
            size_t ob = (size_t)(((par0 * NGRP + g) * 16 + j) * 8 + rb) * 128 + ro4;
            __stcg((float4*)&g_Bv[ob], s);
        }
        // prefetch pre2 for next step
        if (t + 1 < NT) {
#pragma unroll
            for (int i = 0; i < 4; i++) {
                int e = tid + 256 * i;
                int o = e & 127, b = e >> 7;
                p2v[i] = __ldcg(&g_pre2[((size_t)(B0 + b) * NT + t) * 512 + o]);
            }
        }
        // ===== 5) group barrier =====
        __syncthreads();
        if (tid == 0) {
            __threadfence();
            atomicAdd(cnt, 1u);
            while (*(volatile unsigned*)cnt < tgt) { }
        }
        __syncthreads();
        tgt += GBLK;
    }

    // ===== epilogue: out head for t = NT-1 =====
    {
        const int parL = (NT - 1) & 1;
        if (tid < 64) {
            int o = j * 8 + (tid >> 3), b = tid & 7;
            size_t row = (size_t)(B0 + b) * NT + NT - 1;
            float s = __ldcg(&g_pre2[row * 512 + o]);
#pragma unroll
            for (int q = 0; q < 16; q++)
                s += __ldcg(&g_Bv[(((parL * NGRP + g) * 16 + q) * 8 + b) * 128 + o]);
            s = sigmoid_fast(s);
            __stcg(&out[row * 512 + o], s);
        }
    }
}

// ---------------- launch ----------------
extern "C" void kernel_launch(void* const* d_in, const int* in_sizes, int n_in,
                              void* d_out, int out_size) {
    const float* X   = (const float*)d_in[0];
    const float* mem = (const float*)d_in[1];
    const float* W01 = (const float*)d_in[2];
    const float* b01 = (const float*)d_in[3];
    const float* W02 = (const float*)d_in[4];
    const float* b02 = (const float*)d_in[5];
    const float* W12 = (const float*)d_in[6];
    const float* b12 = (const float*)d_in[7];
    const float* Wm1 = (const float*)d_in[8];
    const float* bm1 = (const float*)d_in[9];
    const float* Wm2 = (const float*)d_in[10];
    const float* bm2 = (const float*)d_in[11];
    float* out = (float*)d_out;

    float *pre1, *pre2, *b1, *b2;
    __nv_bfloat16 *X2, *W013, *W023, *Wt3, *At2;
    cudaGetSymbolAddress((void**)&pre1, g_pre1);
    cudaGetSymbolAddress((void**)&pre2, g_pre2);
    cudaGetSymbolAddress((void**)&b1, g_bias1);
    cudaGetSymbolAddress((void**)&b2, g_bias2);
    cudaGetSymbolAddress((void**)&X2, g_X2);
    cudaGetSymbolAddress((void**)&W013, g_W013);
    cudaGetSymbolAddress((void**)&W023, g_W023);
    cudaGetSymbolAddress((void**)&Wt3, g_Wt3);
    cudaGetSymbolAddress((void**)&At2, g_At2);

    const int HG_SMEM = STG * 128 * 40 * 2 * (int)sizeof(__nv_bfloat16);
    cudaFuncSetAttribute(hgemm_kernel, cudaFuncAttributeMaxDynamicSharedMemorySize, HG_SMEM);
    cudaFuncSetAttribute(loop_kernel, cudaFuncAttributeMaxDynamicSharedMemorySize,
                         STOT * (int)sizeof(float));

    prep_all<<<2048, 256>>>(b01, bm1, b02, b12, bm2, mem, X, W01, W02, W12, Wm1, Wm2);
    hgemm_kernel<<<dim3(8, NROWS / 128), 256, HG_SMEM>>>(X2, 1024, 16, W013, 1536,
                                                         pre1, 1024, b1, nullptr, 0);
    hgemm_kernel<<<dim3(4, NROWS / 128), 256, HG_SMEM>>>(X2, 1024, 16, W023, 1536,
                                                         pre2, 512, b2, nullptr, 0);
    loop_kernel<<<NGRP * GBLK, 256, STOT * sizeof(float)>>>(Wm1, W12, Wm2, out);
    hgemm_kernel<<<dim3(3, NROWS / 128), 256, HG_SMEM>>>(At2, 2560, 40, Wt3, 3840,
                                                         out + 128, 512, nullptr,
                                                         pre2 + 128, 512);
}